// round 1
// baseline (speedup 1.0000x reference)
#include <cuda_runtime.h>
#include <cstdint>

#define NB_   32
#define TENC_ 500
#define D_    1024
#define DM_   1024
#define TDEC_ 100
#define E_    256
#define C_    8000
#define G3_   (3*DM_)   // 3072

// ---------------- scratch (device globals; no allocations allowed) ----------
__device__ float g_keys[NB_*TENC_*DM_];      // 65.5 MB
__device__ float g_yemb[NB_*TDEC_*E_];       // 3.3 MB
__device__ float g_gxemb[NB_*TDEC_*G3_];     // 39.3 MB
__device__ float g_qpart[4*NB_*DM_];
__device__ float g_scores[NB_*TENC_];
__device__ float g_ctx[NB_*D_];
__device__ float g_gxpart[4*NB_*G3_];
__device__ float g_h[NB_*DM_];
__device__ float g_H[NB_*TDEC_*DM_];         // 13.1 MB

__device__ __forceinline__ float tanh_approx(float x) {
    float y;
    asm("tanh.approx.f32 %0, %1;" : "=f"(y) : "f"(x));
    return y;
}

// ---------------- generic fp32 SGEMM: C[M,N] = A[M,K] @ B[K,N] + bias[N] ----
// Exact-tile assumption: M%64==0, N%64==0, K%16==0 (holds for all 3 uses).
__global__ __launch_bounds__(256) void sgemm64(
    const float* __restrict__ A, const float* __restrict__ B,
    const float* __restrict__ bias, float* __restrict__ C,
    int M, int N, int K)
{
    __shared__ float As[16][65];   // [k][m]
    __shared__ float Bs[16][68];   // [k][n]
    const int m0 = blockIdx.x * 64;
    const int n0 = blockIdx.y * 64;
    const int tid = threadIdx.x;
    const int tx = tid & 15, ty = tid >> 4;

    const int ra = tid >> 2, ca = (tid & 3) << 2;   // A tile load coords
    const int rb = tid >> 4, cb = (tid & 15) << 2;  // B tile load coords
    const float* Aptr = A + (size_t)(m0 + ra) * K + ca;
    const float* Bptr = B + (size_t)rb * N + n0 + cb;

    float acc[4][4] = {};
    for (int k0 = 0; k0 < K; k0 += 16) {
        float4 a4 = *(const float4*)(Aptr + k0);
        As[ca+0][ra] = a4.x; As[ca+1][ra] = a4.y;
        As[ca+2][ra] = a4.z; As[ca+3][ra] = a4.w;
        float4 b4 = *(const float4*)(Bptr + (size_t)k0 * N);
        *(float4*)&Bs[rb][cb] = b4;
        __syncthreads();
#pragma unroll
        for (int kk = 0; kk < 16; kk++) {
            float a[4], b[4];
#pragma unroll
            for (int i = 0; i < 4; i++) a[i] = As[kk][ty*4 + i];
#pragma unroll
            for (int j = 0; j < 4; j++) b[j] = Bs[kk][tx*4 + j];
#pragma unroll
            for (int i = 0; i < 4; i++)
#pragma unroll
                for (int j = 0; j < 4; j++)
                    acc[i][j] = fmaf(a[i], b[j], acc[i][j]);
        }
        __syncthreads();
    }
#pragma unroll
    for (int i = 0; i < 4; i++) {
        const int row = m0 + ty*4 + i;
#pragma unroll
        for (int j = 0; j < 4; j++) {
            const int col = n0 + tx*4 + j;
            C[(size_t)row * N + col] = acc[i][j] + bias[col];
        }
    }
}

// ---------------- embedding gather: yemb[n*100+t][e] = emb[y[n][t]][e] ------
__global__ void gather_emb(const int* __restrict__ y, const float* __restrict__ emb,
                           float* __restrict__ out)
{
    int idx = blockIdx.x * blockDim.x + threadIdx.x;
    if (idx < NB_*TDEC_*E_) {
        int row = idx >> 8;   // E_ = 256
        int e   = idx & 255;
        out[idx] = emb[(size_t)y[row] * E_ + e];
    }
}

// ---------------- small-M GEMM with K-split partials -----------------------
// part[kz][32][NBcols] += A[32,1024] @ B[1024,NBcols]  (K split into 4x256)
__global__ __launch_bounds__(256) void gemm32_ksplit(
    const float* __restrict__ A, const float* __restrict__ B,
    float* __restrict__ part, int NBcols)
{
    __shared__ float As[32][33];
    __shared__ float Bs[32][33];
    const int j0 = blockIdx.x * 32;
    const int kz = blockIdx.y;
    const int kbase = kz * 256;
    const int tid = threadIdx.x;
    const int tx = tid & 31, ty = tid >> 5;   // ty: 0..7

    float acc[4] = {};
    for (int k0 = 0; k0 < 256; k0 += 32) {
#pragma unroll
        for (int i = 0; i < 4; i++) {
            int lin = tid + i*256;
            int r = lin >> 5, c = lin & 31;
            As[r][c] = A[(size_t)r * 1024 + kbase + k0 + c];
            Bs[r][c] = B[(size_t)(kbase + k0 + r) * NBcols + j0 + c];
        }
        __syncthreads();
#pragma unroll
        for (int kk = 0; kk < 32; kk++) {
            float bvv = Bs[kk][tx];
#pragma unroll
            for (int i = 0; i < 4; i++)
                acc[i] = fmaf(As[ty + i*8][kk], bvv, acc[i]);
        }
        __syncthreads();
    }
#pragma unroll
    for (int i = 0; i < 4; i++)
        part[(size_t)kz * (NB_*NBcols) + (size_t)(ty + i*8) * NBcols + j0 + tx] = acc[i];
}

// ---------------- score: s[n][t] = v . tanh(keys[n][t] + q[n]) + bv ---------
// q[n] reconstructed here from 4 k-split partials + b2 (saves a kernel).
__global__ __launch_bounds__(256) void score_kernel(
    const float* __restrict__ b2, const float* __restrict__ v,
    const float* __restrict__ bv)
{
    __shared__ float qs[DM_];
    __shared__ float vs[DM_];
    const int n = blockIdx.y;
    const int tbase = blockIdx.x * 125;
    const int tid = threadIdx.x;

    for (int d = tid; d < DM_; d += 256) {
        float s = b2[d];
#pragma unroll
        for (int sp = 0; sp < 4; sp++) s += g_qpart[sp*NB_*DM_ + n*DM_ + d];
        qs[d] = s;
        vs[d] = v[d];
    }
    __syncthreads();

    const int w = tid >> 5, lane = tid & 31;
    const float* krow = g_keys + (size_t)n * TENC_ * DM_;
    const float bvv = bv[0];
    for (int t = tbase + w; t < tbase + 125; t += 8) {
        const float* kp = krow + (size_t)t * DM_;
        float acc = 0.f;
#pragma unroll 8
        for (int i = 0; i < 32; i++) {
            int d = lane + i*32;
            acc = fmaf(tanh_approx(kp[d] + qs[d]), vs[d], acc);
        }
#pragma unroll
        for (int off = 16; off; off >>= 1)
            acc += __shfl_xor_sync(0xffffffffu, acc, off);
        if (lane == 0) g_scores[n*TENC_ + t] = acc + bvv;
    }
}

// ---------------- softmax (redundant per block, deterministic) + context ---
__global__ __launch_bounds__(256) void context_kernel(const float* __restrict__ x)
{
    __shared__ float ws[TENC_];
    __shared__ float red[256];
    const int n = blockIdx.y;
    const int d0 = blockIdx.x * 256;
    const int tid = threadIdx.x;

    // max
    float mx = -1e30f;
    for (int t = tid; t < TENC_; t += 256) {
        float s = g_scores[n*TENC_ + t];
        ws[t] = s;
        mx = fmaxf(mx, s);
    }
    red[tid] = mx; __syncthreads();
    for (int s = 128; s; s >>= 1) {
        if (tid < s) red[tid] = fmaxf(red[tid], red[tid+s]);
        __syncthreads();
    }
    mx = red[0];
    __syncthreads();
    // exp + sum
    float lsum = 0.f;
    for (int t = tid; t < TENC_; t += 256) {
        float e = __expf(ws[t] - mx);
        ws[t] = e;
        lsum += e;
    }
    red[tid] = lsum; __syncthreads();
    for (int s = 128; s; s >>= 1) {
        if (tid < s) red[tid] += red[tid+s];
        __syncthreads();
    }
    const float inv = 1.f / red[0];

    // context: ctx[n][d0+tid] = inv * sum_t ws[t] * x[n][t][d0+tid]
    const float* xp = x + (size_t)n * TENC_ * D_ + d0 + tid;
    float a0 = 0.f, a1 = 0.f, a2 = 0.f, a3 = 0.f;
    for (int t = 0; t < TENC_; t += 4) {     // 500 = 4*125
        a0 = fmaf(ws[t+0], xp[(size_t)(t+0)*D_], a0);
        a1 = fmaf(ws[t+1], xp[(size_t)(t+1)*D_], a1);
        a2 = fmaf(ws[t+2], xp[(size_t)(t+2)*D_], a2);
        a3 = fmaf(ws[t+3], xp[(size_t)(t+3)*D_], a3);
    }
    g_ctx[n*D_ + d0 + tid] = ((a0 + a1) + (a2 + a3)) * inv;
}

// ---------------- GRU gates (h_prev == 0: Uh unused, only b_rec) ------------
__global__ __launch_bounds__(256) void gate_kernel(const float* __restrict__ b_rec, int t)
{
    int gid = blockIdx.x * blockDim.x + threadIdx.x;
    if (gid >= NB_*DM_) return;
    const int n = gid >> 10, j = gid & 1023;

    float xz = 0.f, xr = 0.f, xh = 0.f;
#pragma unroll
    for (int s = 0; s < 4; s++) {
        const float* p = g_gxpart + (size_t)s*NB_*G3_ + (size_t)n*G3_;
        xz += p[j]; xr += p[j+1024]; xh += p[j+2048];
    }
    const float* ge = g_gxemb + (size_t)(n*TDEC_ + t) * G3_;  // includes b_in
    xz += ge[j]; xr += ge[j+1024]; xh += ge[j+2048];

    float z  = 1.f / (1.f + __expf(-(xz + b_rec[j])));
    float r  = 1.f / (1.f + __expf(-(xr + b_rec[j+1024])));
    float hh = tanhf(xh + r * b_rec[j+2048]);
    float h  = (1.f - z) * hh;

    g_h[gid] = h;
    g_H[(size_t)(n*TDEC_ + t) * DM_ + j] = h;
}

// ---------------- launch --------------------------------------------------
extern "C" void kernel_launch(void* const* d_in, const int* in_sizes, int n_in,
                              void* d_out, int out_size)
{
    (void)in_sizes; (void)n_in; (void)out_size;
    const float* x    = (const float*)d_in[0];
    const float* m    = (const float*)d_in[1];
    const int*   y    = (const int*)  d_in[2];
    const float* emb  = (const float*)d_in[3];
    const float* W1   = (const float*)d_in[4];
    const float* b1   = (const float*)d_in[5];
    const float* W2   = (const float*)d_in[6];
    const float* b2   = (const float*)d_in[7];
    const float* v    = (const float*)d_in[8];
    const float* bv   = (const float*)d_in[9];
    const float* Wx   = (const float*)d_in[10];
    // d_in[11] = Uh — provably unused (h_prev == 0)
    const float* b_in = (const float*)d_in[12];
    const float* b_rec= (const float*)d_in[13];
    const float* Wo   = (const float*)d_in[14];
    const float* bo   = (const float*)d_in[15];
    float* out = (float*)d_out;

    float *keys, *yemb, *gxemb, *qpart, *ctx, *gxpart, *h, *H;
    cudaGetSymbolAddress((void**)&keys,  g_keys);
    cudaGetSymbolAddress((void**)&yemb,  g_yemb);
    cudaGetSymbolAddress((void**)&gxemb, g_gxemb);
    cudaGetSymbolAddress((void**)&qpart, g_qpart);
    cudaGetSymbolAddress((void**)&ctx,   g_ctx);
    cudaGetSymbolAddress((void**)&gxpart,g_gxpart);
    cudaGetSymbolAddress((void**)&h,     g_h);
    cudaGetSymbolAddress((void**)&H,     g_H);

    // Step-invariant precompute
    gather_emb<<<(NB_*TDEC_*E_ + 255)/256, 256>>>(y, emb, yemb);
    // keys = x @ W1 + b1 : [16000,1024] @ [1024,1024]
    sgemm64<<<dim3(16000/64, 1024/64), 256>>>(x, W1, b1, keys, 16000, 1024, 1024);
    // gxemb = yemb @ Wx[1024:1280,:] + b_in : [3200,256] @ [256,3072]
    sgemm64<<<dim3(3200/64, 3072/64), 256>>>(yemb, Wx + (size_t)1024*G3_, b_in,
                                             gxemb, 3200, 3072, 256);
    // h0 = m
    cudaMemcpyAsync(h, m, (size_t)NB_*DM_*sizeof(float), cudaMemcpyDeviceToDevice);

    // Sequential decode loop
    for (int t = 0; t < TDEC_; t++) {
        gemm32_ksplit<<<dim3(DM_/32, 4), 256>>>(h, W2, qpart, DM_);      // q partials
        score_kernel <<<dim3(4, NB_), 256>>>(b2, v, bv);                 // + q reduce
        context_kernel<<<dim3(4, NB_), 256>>>(x);                        // + softmax
        gemm32_ksplit<<<dim3(G3_/32, 4), 256>>>(ctx, Wx, gxpart, G3_);   // gx_ctx partials
        gate_kernel  <<<NB_*DM_/256, 256>>>(b_rec, t);                   // h_t, H[t]
    }

    // out = H @ Wo + bo : [3200,1024] @ [1024,8000]
    sgemm64<<<dim3(3200/64, 8000/64), 256>>>(H, Wo, bo, out, 3200, 8000, 1024);
}

// round 3
// speedup vs baseline: 1.0897x; 1.0897x over previous
#include <cuda_runtime.h>
#include <cstdint>

#define NB_   32
#define TENC_ 500
#define D_    1024
#define DM_   1024
#define TDEC_ 100
#define E_    256
#define C_    8000
#define G3_   (3*DM_)   // 3072

// ---------------- scratch (device globals; no allocations allowed) ----------
__device__ float g_keys[NB_*TENC_*DM_];      // 65.5 MB
__device__ float g_W2t[DM_*DM_];             // W2^T [j][k]
__device__ float g_Wxt[G3_*DM_];             // Wx^T (context rows) [j][k]
__device__ float g_yemb[NB_*TDEC_*E_];
__device__ float g_gxemb[NB_*TDEC_*G3_];     // 39.3 MB
__device__ float g_qpart[4*NB_*DM_];
__device__ float g_scores[NB_*TENC_];
__device__ float g_ctx[NB_*D_];
__device__ float g_gxpart[4*NB_*G3_];
__device__ float g_h[NB_*DM_];
__device__ float g_H[NB_*TDEC_*DM_];         // 13.1 MB

__device__ __forceinline__ float tanh_approx(float x) {
    float y;
    asm("tanh.approx.f32 %0, %1;" : "=f"(y) : "f"(x));
    return y;
}

// ---------------- generic fp32 SGEMM: C[M,N] = A[M,K] @ B[K,N] + bias[N] ----
__global__ __launch_bounds__(256) void sgemm64(
    const float* __restrict__ A, const float* __restrict__ B,
    const float* __restrict__ bias, float* __restrict__ C,
    int M, int N, int K)
{
    __shared__ float As[16][65];
    __shared__ float Bs[16][68];
    const int m0 = blockIdx.x * 64;
    const int n0 = blockIdx.y * 64;
    const int tid = threadIdx.x;
    const int tx = tid & 15, ty = tid >> 4;

    const int ra = tid >> 2, ca = (tid & 3) << 2;
    const int rb = tid >> 4, cb = (tid & 15) << 2;
    const float* Aptr = A + (size_t)(m0 + ra) * K + ca;
    const float* Bptr = B + (size_t)rb * N + n0 + cb;

    float acc[4][4] = {};
    for (int k0 = 0; k0 < K; k0 += 16) {
        float4 a4 = *(const float4*)(Aptr + k0);
        As[ca+0][ra] = a4.x; As[ca+1][ra] = a4.y;
        As[ca+2][ra] = a4.z; As[ca+3][ra] = a4.w;
        float4 b4 = *(const float4*)(Bptr + (size_t)k0 * N);
        *(float4*)&Bs[rb][cb] = b4;
        __syncthreads();
#pragma unroll
        for (int kk = 0; kk < 16; kk++) {
            float a[4], b[4];
#pragma unroll
            for (int i = 0; i < 4; i++) a[i] = As[kk][ty*4 + i];
#pragma unroll
            for (int j = 0; j < 4; j++) b[j] = Bs[kk][tx*4 + j];
#pragma unroll
            for (int i = 0; i < 4; i++)
#pragma unroll
                for (int j = 0; j < 4; j++)
                    acc[i][j] = fmaf(a[i], b[j], acc[i][j]);
        }
        __syncthreads();
    }
#pragma unroll
    for (int i = 0; i < 4; i++) {
        const int row = m0 + ty*4 + i;
#pragma unroll
        for (int j = 0; j < 4; j++) {
            const int col = n0 + tx*4 + j;
            C[(size_t)row * N + col] = acc[i][j] + bias[col];
        }
    }
}

// ---------------- transpose fp32: dst[c][r] = src[r][c] --------------------
__global__ void transpose_f32(const float* __restrict__ src,
                              float* __restrict__ dst,
                              int R, int ldsrc)
{
    __shared__ float tile[32][33];
    const int r0 = blockIdx.y * 32, c0 = blockIdx.x * 32;
    for (int i = threadIdx.y; i < 32; i += 8)
        tile[i][threadIdx.x] = src[(size_t)(r0 + i) * ldsrc + c0 + threadIdx.x];
    __syncthreads();
    for (int i = threadIdx.y; i < 32; i += 8)
        dst[(size_t)(c0 + i) * R + r0 + threadIdx.x] = tile[threadIdx.x][i];
}

// ---------------- embedding gather ------------------------------------------
__global__ void gather_emb(const int* __restrict__ y, const float* __restrict__ emb,
                           float* __restrict__ out)
{
    int idx = blockIdx.x * blockDim.x + threadIdx.x;
    if (idx < NB_*TDEC_*E_) {
        int row = idx >> 8;
        int e   = idx & 255;
        out[idx] = emb[(size_t)y[row] * E_ + e];
    }
}

// ---------------- skinny GEMM: part[kz][n][j] = sum_k A[n][k]*Bt[j][k] ------
// A: [32][1024] fp32. Bt: [NBcols][1024] fp32 (transposed). K split 4x256.
__global__ __launch_bounds__(256) void gemm_skinny(
    const float* __restrict__ A, const float* __restrict__ Bt,
    float* __restrict__ part, int NBcols)
{
    __shared__ float As[256][36];   // [kk][n]
    const int j0 = blockIdx.x * 32;
    const int kz = blockIdx.y;
    const int kbase = kz * 256;
    const int tid = threadIdx.x;

    // stage A slice: As[kk][n] = A[n][kbase+kk]
#pragma unroll 8
    for (int i = 0; i < 32; i++)
        As[tid][i] = A[(size_t)i * 1024 + kbase + tid];
    __syncthreads();

    const int tx = tid & 31, ty = tid >> 5;     // tx: column, ty: n-group (0..7)
    const int j = j0 + tx;
    const float4* bp = (const float4*)(Bt + (size_t)j * 1024 + kbase);

    float acc0 = 0.f, acc1 = 0.f, acc2 = 0.f, acc3 = 0.f;
#pragma unroll 8
    for (int kk = 0; kk < 256; kk += 4) {
        float4 b4 = bp[kk >> 2];
        float b[4] = {b4.x, b4.y, b4.z, b4.w};
#pragma unroll
        for (int u = 0; u < 4; u++) {
            float4 a = *(const float4*)&As[kk + u][ty * 4];
            acc0 = fmaf(b[u], a.x, acc0);
            acc1 = fmaf(b[u], a.y, acc1);
            acc2 = fmaf(b[u], a.z, acc2);
            acc3 = fmaf(b[u], a.w, acc3);
        }
    }
    const int n = ty * 4;
    float* po = part + (size_t)(kz * 32 + n) * NBcols + j;
    po[0]                 = acc0;
    po[(size_t)NBcols]    = acc1;
    po[(size_t)2*NBcols]  = acc2;
    po[(size_t)3*NBcols]  = acc3;
}

// ---------------- score: s[n][t] = v . tanh(keys[n][t] + q[n]) + bv ---------
__global__ __launch_bounds__(256) void score_kernel(
    const float* __restrict__ b2, const float* __restrict__ v,
    const float* __restrict__ bv)
{
    __shared__ float qs[DM_];
    __shared__ float vs[DM_];
    const int n = blockIdx.y;
    const int tbase = blockIdx.x * 20;
    const int tid = threadIdx.x;

    for (int d = tid; d < DM_; d += 256) {
        float s = b2[d];
#pragma unroll
        for (int sp = 0; sp < 4; sp++) s += g_qpart[sp*NB_*DM_ + n*DM_ + d];
        qs[d] = s;
        vs[d] = v[d];
    }
    __syncthreads();

    const int w = tid >> 5, lane = tid & 31;
    const float bvv = bv[0];
    for (int t = tbase + w; t < tbase + 20; t += 8) {
        const float4* kp = (const float4*)(g_keys + ((size_t)(n*TENC_ + t) << 10));
        float acc = 0.f;
#pragma unroll
        for (int i = 0; i < 8; i++) {
            float4 k4 = kp[lane + (i << 5)];
            const int d0 = (lane + (i << 5)) << 2;
            float4 q4 = *(const float4*)&qs[d0];
            float4 v4 = *(const float4*)&vs[d0];
            acc = fmaf(tanh_approx(k4.x + q4.x), v4.x, acc);
            acc = fmaf(tanh_approx(k4.y + q4.y), v4.y, acc);
            acc = fmaf(tanh_approx(k4.z + q4.z), v4.z, acc);
            acc = fmaf(tanh_approx(k4.w + q4.w), v4.w, acc);
        }
#pragma unroll
        for (int off = 16; off; off >>= 1)
            acc += __shfl_xor_sync(0xffffffffu, acc, off);
        if (lane == 0) g_scores[n*TENC_ + t] = acc + bvv;
    }
}

// ---------------- softmax (redundant per block, deterministic) + context ---
__global__ __launch_bounds__(256) void context_kernel(const float* __restrict__ x)
{
    __shared__ float ws[TENC_];
    __shared__ float red[256];
    const int n = blockIdx.y;
    const int d0 = blockIdx.x * 256;
    const int tid = threadIdx.x;

    float mx = -1e30f;
    for (int t = tid; t < TENC_; t += 256) {
        float s = g_scores[n*TENC_ + t];
        ws[t] = s;
        mx = fmaxf(mx, s);
    }
    red[tid] = mx; __syncthreads();
    for (int s = 128; s; s >>= 1) {
        if (tid < s) red[tid] = fmaxf(red[tid], red[tid+s]);
        __syncthreads();
    }
    mx = red[0];
    __syncthreads();
    float lsum = 0.f;
    for (int t = tid; t < TENC_; t += 256) {
        float e = __expf(ws[t] - mx);
        ws[t] = e;
        lsum += e;
    }
    red[tid] = lsum; __syncthreads();
    for (int s = 128; s; s >>= 1) {
        if (tid < s) red[tid] += red[tid+s];
        __syncthreads();
    }
    const float inv = 1.f / red[0];

    const float* xp = x + (size_t)n * TENC_ * D_ + d0 + tid;
    float a[10];
#pragma unroll
    for (int u = 0; u < 10; u++) a[u] = 0.f;
    for (int t = 0; t < TENC_; t += 10) {   // 500 = 50*10, MLP=10
#pragma unroll
        for (int u = 0; u < 10; u++)
            a[u] = fmaf(ws[t+u], xp[(size_t)(t+u)*D_], a[u]);
    }
    float s0 = (a[0]+a[1]) + (a[2]+a[3]);
    float s1 = (a[4]+a[5]) + (a[6]+a[7]);
    float s2 = a[8]+a[9];
    g_ctx[n*D_ + d0 + tid] = (s0 + s1 + s2) * inv;
}

// ---------------- GRU gates (h_prev == 0: Uh unused, only b_rec) ------------
__global__ __launch_bounds__(256) void gate_kernel(const float* __restrict__ b_rec, int t)
{
    int gid = blockIdx.x * blockDim.x + threadIdx.x;
    if (gid >= NB_*DM_) return;
    const int n = gid >> 10, j = gid & 1023;

    float xz = 0.f, xr = 0.f, xh = 0.f;
#pragma unroll
    for (int s = 0; s < 4; s++) {
        const float* p = g_gxpart + (size_t)s*NB_*G3_ + (size_t)n*G3_;
        xz += p[j]; xr += p[j+1024]; xh += p[j+2048];
    }
    const float* ge = g_gxemb + (size_t)(n*TDEC_ + t) * G3_;
    xz += ge[j]; xr += ge[j+1024]; xh += ge[j+2048];

    float z  = 1.f / (1.f + __expf(-(xz + b_rec[j])));
    float r  = 1.f / (1.f + __expf(-(xr + b_rec[j+1024])));
    float hh = tanhf(xh + r * b_rec[j+2048]);
    float h  = (1.f - z) * hh;

    g_h[gid] = h;
    g_H[(size_t)(n*TDEC_ + t) * DM_ + j] = h;
}

// ---------------- launch -----------------------------------------------------
extern "C" void kernel_launch(void* const* d_in, const int* in_sizes, int n_in,
                              void* d_out, int out_size)
{
    (void)in_sizes; (void)n_in; (void)out_size;
    const float* x    = (const float*)d_in[0];
    const float* m    = (const float*)d_in[1];
    const int*   y    = (const int*)  d_in[2];
    const float* emb  = (const float*)d_in[3];
    const float* W1   = (const float*)d_in[4];
    const float* b1   = (const float*)d_in[5];
    const float* W2   = (const float*)d_in[6];
    const float* b2   = (const float*)d_in[7];
    const float* v    = (const float*)d_in[8];
    const float* bv   = (const float*)d_in[9];
    const float* Wx   = (const float*)d_in[10];
    // d_in[11] = Uh — provably unused (h_prev == 0)
    const float* b_in = (const float*)d_in[12];
    const float* b_rec= (const float*)d_in[13];
    const float* Wo   = (const float*)d_in[14];
    const float* bo   = (const float*)d_in[15];
    float* out = (float*)d_out;

    float *keys, *W2t, *Wxt, *yemb, *gxemb, *qpart, *ctx, *gxpart, *h, *H;
    cudaGetSymbolAddress((void**)&keys,  g_keys);
    cudaGetSymbolAddress((void**)&W2t,   g_W2t);
    cudaGetSymbolAddress((void**)&Wxt,   g_Wxt);
    cudaGetSymbolAddress((void**)&yemb,  g_yemb);
    cudaGetSymbolAddress((void**)&gxemb, g_gxemb);
    cudaGetSymbolAddress((void**)&qpart, g_qpart);
    cudaGetSymbolAddress((void**)&ctx,   g_ctx);
    cudaGetSymbolAddress((void**)&gxpart,g_gxpart);
    cudaGetSymbolAddress((void**)&h,     g_h);
    cudaGetSymbolAddress((void**)&H,     g_H);

    // ---- step-invariant precompute ----
    gather_emb<<<(NB_*TDEC_*E_ + 255)/256, 256>>>(y, emb, yemb);
    // keys = x @ W1 + b1 : [16000,1024]
    sgemm64<<<dim3(16000/64, 1024/64), 256>>>(x, W1, b1, keys, 16000, 1024, 1024);
    // gxemb = yemb @ Wx[1024:1280,:] + b_in
    sgemm64<<<dim3(3200/64, 3072/64), 256>>>(yemb, Wx + (size_t)1024*G3_,
                                             b_in, gxemb, 3200, 3072, 256);
    // fp32 transposed weights for skinny GEMMs
    transpose_f32<<<dim3(1024/32, 1024/32), dim3(32,8)>>>(W2, W2t, 1024, 1024);
    transpose_f32<<<dim3(3072/32, 1024/32), dim3(32,8)>>>(Wx, Wxt, 1024, 3072);
    cudaMemcpyAsync(h, m, (size_t)NB_*DM_*sizeof(float), cudaMemcpyDeviceToDevice);

    // ---- sequential decode loop ----
    for (int t = 0; t < TDEC_; t++) {
        gemm_skinny<<<dim3(DM_/32, 4), 256>>>(h, W2t, qpart, DM_);
        score_kernel<<<dim3(TENC_/20, NB_), 256>>>(b2, v, bv);
        context_kernel<<<dim3(4, NB_), 256>>>(x);
        gemm_skinny<<<dim3(G3_/32, 4), 256>>>(ctx, Wxt, gxpart, G3_);
        gate_kernel<<<NB_*DM_/256, 256>>>(b_rec, t);
    }

    // ---- out = H @ Wo + bo : [3200,1024] @ [1024,8000] ----
    sgemm64<<<dim3(3200/64, 8000/64), 256>>>(H, Wo, bo, out, 3200, 8000, 1024);
}

// round 4
// speedup vs baseline: 1.1196x; 1.0275x over previous
#include <cuda_runtime.h>
#include <cstdint>

#define NB_   32
#define TENC_ 500
#define D_    1024
#define DM_   1024
#define TDEC_ 100
#define E_    256
#define C_    8000
#define G3_   (3*DM_)   // 3072

// ---------------- scratch (device globals; no allocations allowed) ----------
__device__ float g_keys[NB_*TENC_*DM_];      // 65.5 MB
__device__ float g_W2t[DM_*DM_];             // W2^T [j][k]
__device__ float g_Wxt[G3_*DM_];             // Wx^T (context rows) [j][k]
__device__ float g_yemb[NB_*TDEC_*E_];
__device__ float g_gxemb[NB_*TDEC_*G3_];     // 39.3 MB
__device__ float g_qpart[4*NB_*DM_];
__device__ float g_scores[NB_*TENC_];
__device__ float g_ctx[NB_*D_];
__device__ float g_gxpart[4*NB_*G3_];
__device__ float g_h[NB_*DM_];
__device__ float g_H[NB_*TDEC_*DM_];         // 13.1 MB

__device__ __forceinline__ float tanh_approx(float x) {
    float y;
    asm("tanh.approx.f32 %0, %1;" : "=f"(y) : "f"(x));
    return y;
}

// ---------------- high-throughput fp32 SGEMM ---------------------------------
// C[M,N] = A[M,K] @ B[K,N] + bias[N]
// 128x128 block tile, BK=16, 256 threads, 8x8 per thread, double-buffered smem.
// Requires: M % 128 == 0, K % 16 == 0, N % 4 == 0 (N boundary guarded).
__global__ __launch_bounds__(256, 2) void sgemm128(
    const float* __restrict__ A, const float* __restrict__ B,
    const float* __restrict__ bias, float* __restrict__ C,
    int M, int N, int K)
{
    __shared__ float As[2][16][132];   // [buf][k][m], padded
    __shared__ float Bs[2][16][128];   // [buf][k][n]

    const int m0 = blockIdx.x * 128;
    const int n0 = blockIdx.y * 128;
    const int tid = threadIdx.x;
    const int tx = tid & 15, ty = tid >> 4;

    // A tile: 128 rows x 16 cols -> 512 float4, 2 per thread
    const int ar  = tid >> 2;          // 0..63 (+64 for second)
    const int ac4 = (tid & 3) << 2;    // 0,4,8,12
    // B tile: 16 rows x 128 cols -> 512 float4, 2 per thread
    const int br  = tid >> 5;          // 0..7 (+8 for second)
    const int bc  = (tid & 31) << 2;   // 0..124

    const int nk = K >> 4;
    const bool bcol_ok = (n0 + bc) < N;   // N % 4 == 0 => whole float4 in/out

    // ---- prologue: load tile 0 into buf 0 ----
    {
        float4 a0 = *(const float4*)(A + (size_t)(m0 + ar)      * K + ac4);
        float4 a1 = *(const float4*)(A + (size_t)(m0 + ar + 64) * K + ac4);
        As[0][ac4+0][ar]    = a0.x; As[0][ac4+1][ar]    = a0.y;
        As[0][ac4+2][ar]    = a0.z; As[0][ac4+3][ar]    = a0.w;
        As[0][ac4+0][ar+64] = a1.x; As[0][ac4+1][ar+64] = a1.y;
        As[0][ac4+2][ar+64] = a1.z; As[0][ac4+3][ar+64] = a1.w;
        float4 b0 = bcol_ok ? *(const float4*)(B + (size_t)br      * N + n0 + bc)
                            : make_float4(0.f,0.f,0.f,0.f);
        float4 b1 = bcol_ok ? *(const float4*)(B + (size_t)(br+8)  * N + n0 + bc)
                            : make_float4(0.f,0.f,0.f,0.f);
        *(float4*)&Bs[0][br][bc]   = b0;
        *(float4*)&Bs[0][br+8][bc] = b1;
    }
    __syncthreads();

    float acc[8][8] = {};

    for (int kt = 0; kt < nk; kt++) {
        const int buf = kt & 1;
        const int nxt = buf ^ 1;
        const bool has_next = (kt + 1) < nk;

        float4 pa0, pa1, pb0, pb1;
        if (has_next) {
            const int k0 = (kt + 1) << 4;
            pa0 = *(const float4*)(A + (size_t)(m0 + ar)      * K + k0 + ac4);
            pa1 = *(const float4*)(A + (size_t)(m0 + ar + 64) * K + k0 + ac4);
            pb0 = bcol_ok ? *(const float4*)(B + (size_t)(k0 + br)     * N + n0 + bc)
                          : make_float4(0.f,0.f,0.f,0.f);
            pb1 = bcol_ok ? *(const float4*)(B + (size_t)(k0 + br + 8) * N + n0 + bc)
                          : make_float4(0.f,0.f,0.f,0.f);
        }

#pragma unroll
        for (int kk = 0; kk < 16; kk++) {
            float a[8], b[8];
            *(float4*)&a[0] = *(const float4*)&As[buf][kk][ty*8];
            *(float4*)&a[4] = *(const float4*)&As[buf][kk][ty*8 + 4];
            *(float4*)&b[0] = *(const float4*)&Bs[buf][kk][tx*8];
            *(float4*)&b[4] = *(const float4*)&Bs[buf][kk][tx*8 + 4];
#pragma unroll
            for (int i = 0; i < 8; i++)
#pragma unroll
                for (int j = 0; j < 8; j++)
                    acc[i][j] = fmaf(a[i], b[j], acc[i][j]);
        }

        if (has_next) {
            As[nxt][ac4+0][ar]    = pa0.x; As[nxt][ac4+1][ar]    = pa0.y;
            As[nxt][ac4+2][ar]    = pa0.z; As[nxt][ac4+3][ar]    = pa0.w;
            As[nxt][ac4+0][ar+64] = pa1.x; As[nxt][ac4+1][ar+64] = pa1.y;
            As[nxt][ac4+2][ar+64] = pa1.z; As[nxt][ac4+3][ar+64] = pa1.w;
            *(float4*)&Bs[nxt][br][bc]   = pb0;
            *(float4*)&Bs[nxt][br+8][bc] = pb1;
        }
        __syncthreads();
    }

    // ---- epilogue: C = acc + bias ----
#pragma unroll
    for (int i = 0; i < 8; i++) {
        const int row = m0 + ty*8 + i;
#pragma unroll
        for (int j4 = 0; j4 < 2; j4++) {
            const int col = n0 + tx*8 + j4*4;
            if (col < N) {
                float4 bv = *(const float4*)(bias + col);
                float4 o;
                o.x = acc[i][j4*4+0] + bv.x;
                o.y = acc[i][j4*4+1] + bv.y;
                o.z = acc[i][j4*4+2] + bv.z;
                o.w = acc[i][j4*4+3] + bv.w;
                *(float4*)(C + (size_t)row * N + col) = o;
            }
        }
    }
}

// ---------------- transpose fp32: dst[c][r] = src[r][c] --------------------
__global__ void transpose_f32(const float* __restrict__ src,
                              float* __restrict__ dst,
                              int R, int ldsrc)
{
    __shared__ float tile[32][33];
    const int r0 = blockIdx.y * 32, c0 = blockIdx.x * 32;
    for (int i = threadIdx.y; i < 32; i += 8)
        tile[i][threadIdx.x] = src[(size_t)(r0 + i) * ldsrc + c0 + threadIdx.x];
    __syncthreads();
    for (int i = threadIdx.y; i < 32; i += 8)
        dst[(size_t)(c0 + i) * R + r0 + threadIdx.x] = tile[threadIdx.x][i];
}

// ---------------- embedding gather ------------------------------------------
__global__ void gather_emb(const int* __restrict__ y, const float* __restrict__ emb,
                           float* __restrict__ out)
{
    int idx = blockIdx.x * blockDim.x + threadIdx.x;
    if (idx < NB_*TDEC_*E_) {
        int row = idx >> 8;
        int e   = idx & 255;
        out[idx] = emb[(size_t)y[row] * E_ + e];
    }
}

// ---------------- skinny GEMM: part[kz][n][j] = sum_k A[n][k]*Bt[j][k] ------
__global__ __launch_bounds__(256) void gemm_skinny(
    const float* __restrict__ A, const float* __restrict__ Bt,
    float* __restrict__ part, int NBcols)
{
    __shared__ float As[256][36];   // [kk][n]
    const int j0 = blockIdx.x * 32;
    const int kz = blockIdx.y;
    const int kbase = kz * 256;
    const int tid = threadIdx.x;

#pragma unroll 8
    for (int i = 0; i < 32; i++)
        As[tid][i] = A[(size_t)i * 1024 + kbase + tid];
    __syncthreads();

    const int tx = tid & 31, ty = tid >> 5;
    const int j = j0 + tx;
    const float4* bp = (const float4*)(Bt + (size_t)j * 1024 + kbase);

    float acc0 = 0.f, acc1 = 0.f, acc2 = 0.f, acc3 = 0.f;
#pragma unroll 8
    for (int kk = 0; kk < 256; kk += 4) {
        float4 b4 = bp[kk >> 2];
        float b[4] = {b4.x, b4.y, b4.z, b4.w};
#pragma unroll
        for (int u = 0; u < 4; u++) {
            float4 a = *(const float4*)&As[kk + u][ty * 4];
            acc0 = fmaf(b[u], a.x, acc0);
            acc1 = fmaf(b[u], a.y, acc1);
            acc2 = fmaf(b[u], a.z, acc2);
            acc3 = fmaf(b[u], a.w, acc3);
        }
    }
    const int n = ty * 4;
    float* po = part + (size_t)(kz * 32 + n) * NBcols + j;
    po[0]                 = acc0;
    po[(size_t)NBcols]    = acc1;
    po[(size_t)2*NBcols]  = acc2;
    po[(size_t)3*NBcols]  = acc3;
}

// ---------------- score: s[n][t] = v . tanh(keys[n][t] + q[n]) + bv ---------
__global__ __launch_bounds__(256) void score_kernel(
    const float* __restrict__ b2, const float* __restrict__ v,
    const float* __restrict__ bv)
{
    __shared__ float qs[DM_];
    __shared__ float vs[DM_];
    const int n = blockIdx.y;
    const int tbase = blockIdx.x * 20;
    const int tid = threadIdx.x;

    for (int d = tid; d < DM_; d += 256) {
        float s = b2[d];
#pragma unroll
        for (int sp = 0; sp < 4; sp++) s += g_qpart[sp*NB_*DM_ + n*DM_ + d];
        qs[d] = s;
        vs[d] = v[d];
    }
    __syncthreads();

    const int w = tid >> 5, lane = tid & 31;
    const float bvv = bv[0];
    for (int t = tbase + w; t < tbase + 20; t += 8) {
        const float4* kp = (const float4*)(g_keys + ((size_t)(n*TENC_ + t) << 10));
        float acc = 0.f;
#pragma unroll
        for (int i = 0; i < 8; i++) {
            float4 k4 = kp[lane + (i << 5)];
            const int d0 = (lane + (i << 5)) << 2;
            float4 q4 = *(const float4*)&qs[d0];
            float4 v4 = *(const float4*)&vs[d0];
            acc = fmaf(tanh_approx(k4.x + q4.x), v4.x, acc);
            acc = fmaf(tanh_approx(k4.y + q4.y), v4.y, acc);
            acc = fmaf(tanh_approx(k4.z + q4.z), v4.z, acc);
            acc = fmaf(tanh_approx(k4.w + q4.w), v4.w, acc);
        }
#pragma unroll
        for (int off = 16; off; off >>= 1)
            acc += __shfl_xor_sync(0xffffffffu, acc, off);
        if (lane == 0) g_scores[n*TENC_ + t] = acc + bvv;
    }
}

// ---------------- softmax (redundant per block, deterministic) + context ---
__global__ __launch_bounds__(256) void context_kernel(const float* __restrict__ x)
{
    __shared__ float ws[TENC_];
    __shared__ float red[256];
    const int n = blockIdx.y;
    const int d0 = blockIdx.x * 256;
    const int tid = threadIdx.x;

    float mx = -1e30f;
    for (int t = tid; t < TENC_; t += 256) {
        float s = g_scores[n*TENC_ + t];
        ws[t] = s;
        mx = fmaxf(mx, s);
    }
    red[tid] = mx; __syncthreads();
    for (int s = 128; s; s >>= 1) {
        if (tid < s) red[tid] = fmaxf(red[tid], red[tid+s]);
        __syncthreads();
    }
    mx = red[0];
    __syncthreads();
    float lsum = 0.f;
    for (int t = tid; t < TENC_; t += 256) {
        float e = __expf(ws[t] - mx);
        ws[t] = e;
        lsum += e;
    }
    red[tid] = lsum; __syncthreads();
    for (int s = 128; s; s >>= 1) {
        if (tid < s) red[tid] += red[tid+s];
        __syncthreads();
    }
    const float inv = 1.f / red[0];

    const float* xp = x + (size_t)n * TENC_ * D_ + d0 + tid;
    float a[10];
#pragma unroll
    for (int u = 0; u < 10; u++) a[u] = 0.f;
    for (int t = 0; t < TENC_; t += 10) {   // 500 = 50*10
#pragma unroll
        for (int u = 0; u < 10; u++)
            a[u] = fmaf(ws[t+u], xp[(size_t)(t+u)*D_], a[u]);
    }
    float s0 = (a[0]+a[1]) + (a[2]+a[3]);
    float s1 = (a[4]+a[5]) + (a[6]+a[7]);
    float s2 = a[8]+a[9];
    g_ctx[n*D_ + d0 + tid] = (s0 + s1 + s2) * inv;
}

// ---------------- GRU gates (h_prev == 0: Uh unused, only b_rec) ------------
__global__ __launch_bounds__(256) void gate_kernel(const float* __restrict__ b_rec, int t)
{
    int gid = blockIdx.x * blockDim.x + threadIdx.x;
    if (gid >= NB_*DM_) return;
    const int n = gid >> 10, j = gid & 1023;

    float xz = 0.f, xr = 0.f, xh = 0.f;
#pragma unroll
    for (int s = 0; s < 4; s++) {
        const float* p = g_gxpart + (size_t)s*NB_*G3_ + (size_t)n*G3_;
        xz += p[j]; xr += p[j+1024]; xh += p[j+2048];
    }
    const float* ge = g_gxemb + (size_t)(n*TDEC_ + t) * G3_;
    xz += ge[j]; xr += ge[j+1024]; xh += ge[j+2048];

    float z  = 1.f / (1.f + __expf(-(xz + b_rec[j])));
    float r  = 1.f / (1.f + __expf(-(xr + b_rec[j+1024])));
    float hh = tanhf(xh + r * b_rec[j+2048]);
    float h  = (1.f - z) * hh;

    g_h[gid] = h;
    g_H[(size_t)(n*TDEC_ + t) * DM_ + j] = h;
}

// ---------------- launch -----------------------------------------------------
extern "C" void kernel_launch(void* const* d_in, const int* in_sizes, int n_in,
                              void* d_out, int out_size)
{
    (void)in_sizes; (void)n_in; (void)out_size;
    const float* x    = (const float*)d_in[0];
    const float* m    = (const float*)d_in[1];
    const int*   y    = (const int*)  d_in[2];
    const float* emb  = (const float*)d_in[3];
    const float* W1   = (const float*)d_in[4];
    const float* b1   = (const float*)d_in[5];
    const float* W2   = (const float*)d_in[6];
    const float* b2   = (const float*)d_in[7];
    const float* v    = (const float*)d_in[8];
    const float* bv   = (const float*)d_in[9];
    const float* Wx   = (const float*)d_in[10];
    // d_in[11] = Uh — provably unused (h_prev == 0)
    const float* b_in = (const float*)d_in[12];
    const float* b_rec= (const float*)d_in[13];
    const float* Wo   = (const float*)d_in[14];
    const float* bo   = (const float*)d_in[15];
    float* out = (float*)d_out;

    float *keys, *W2t, *Wxt, *yemb, *gxemb, *qpart, *ctx, *gxpart, *h, *H;
    cudaGetSymbolAddress((void**)&keys,  g_keys);
    cudaGetSymbolAddress((void**)&W2t,   g_W2t);
    cudaGetSymbolAddress((void**)&Wxt,   g_Wxt);
    cudaGetSymbolAddress((void**)&yemb,  g_yemb);
    cudaGetSymbolAddress((void**)&gxemb, g_gxemb);
    cudaGetSymbolAddress((void**)&qpart, g_qpart);
    cudaGetSymbolAddress((void**)&ctx,   g_ctx);
    cudaGetSymbolAddress((void**)&gxpart,g_gxpart);
    cudaGetSymbolAddress((void**)&h,     g_h);
    cudaGetSymbolAddress((void**)&H,     g_H);

    // ---- step-invariant precompute ----
    gather_emb<<<(NB_*TDEC_*E_ + 255)/256, 256>>>(y, emb, yemb);
    // keys = x @ W1 + b1 : [16000,1024] @ [1024,1024]
    sgemm128<<<dim3(16000/128, 1024/128), 256>>>(x, W1, b1, keys, 16000, 1024, 1024);
    // gxemb = yemb @ Wx[1024:1280,:] + b_in : [3200,256] @ [256,3072]
    sgemm128<<<dim3(3200/128, 3072/128), 256>>>(yemb, Wx + (size_t)1024*G3_,
                                                b_in, gxemb, 3200, 3072, 256);
    // fp32 transposed weights for skinny GEMMs
    transpose_f32<<<dim3(1024/32, 1024/32), dim3(32,8)>>>(W2, W2t, 1024, 1024);
    transpose_f32<<<dim3(3072/32, 1024/32), dim3(32,8)>>>(Wx, Wxt, 1024, 3072);
    cudaMemcpyAsync(h, m, (size_t)NB_*DM_*sizeof(float), cudaMemcpyDeviceToDevice);

    // ---- sequential decode loop ----
    for (int t = 0; t < TDEC_; t++) {
        gemm_skinny<<<dim3(DM_/32, 4), 256>>>(h, W2t, qpart, DM_);
        score_kernel<<<dim3(TENC_/20, NB_), 256>>>(b2, v, bv);
        context_kernel<<<dim3(4, NB_), 256>>>(x);
        gemm_skinny<<<dim3(G3_/32, 4), 256>>>(ctx, Wxt, gxpart, G3_);
        gate_kernel<<<NB_*DM_/256, 256>>>(b_rec, t);
    }

    // ---- out = H @ Wo + bo : [3200,1024] @ [1024,8000] ----
    sgemm128<<<dim3(3200/128, (8000 + 127)/128), 256>>>(H, Wo, bo, out,
                                                        3200, 8000, 1024);
}

// round 5
// speedup vs baseline: 2.1009x; 1.8764x over previous
#include <cuda_runtime.h>
#include <cuda_fp16.h>
#include <cstdint>

#define NB_   32
#define TENC_ 500
#define D_    1024
#define DM_   1024
#define TDEC_ 100
#define E_    256
#define C_    8000
#define G3_   (3*DM_)   // 3072

// ---------------- scratch (device globals; no allocations allowed) ----------
__device__ __half g_keysh[NB_*TENC_*DM_];    // 32.8 MB fp16
__device__ __half g_xh[NB_*TENC_*D_];        // 32.8 MB fp16 copy of x
__device__ __half g_W2t[DM_*DM_];            // W2^T fp16 [j][k]
__device__ __half g_Wxt[G3_*DM_];            // Wx^T (context rows) fp16 [j][k]
__device__ float g_yemb[NB_*TDEC_*E_];
__device__ float g_gxemb[NB_*TDEC_*G3_];     // 39.3 MB
__device__ float g_qpart[4*NB_*DM_];
__device__ float g_scores[NB_*TENC_];
__device__ float g_ctxpart[4*NB_*D_];        // 4 t-chunk partials
__device__ float g_gxpart[4*NB_*G3_];
__device__ float g_h[NB_*DM_];
__device__ float g_H[NB_*TDEC_*DM_];         // 13.1 MB

__device__ __forceinline__ float tanh_approx(float x) {
    float y;
    asm("tanh.approx.f32 %0, %1;" : "=f"(y) : "f"(x));
    return y;
}

// ---------------- high-throughput fp32 SGEMM ---------------------------------
// C[M,N] = A[M,K] @ B[K,N] + bias[N]; OutT in {float, __half}.
// 128x128 tile, BK=16, 256 threads, 8x8/thread, double-buffered.
template <typename OutT>
__global__ __launch_bounds__(256, 2) void sgemm128(
    const float* __restrict__ A, const float* __restrict__ B,
    const float* __restrict__ bias, OutT* __restrict__ C,
    int M, int N, int K)
{
    __shared__ float As[2][16][132];
    __shared__ float Bs[2][16][128];

    const int m0 = blockIdx.x * 128;
    const int n0 = blockIdx.y * 128;
    const int tid = threadIdx.x;
    const int tx = tid & 15, ty = tid >> 4;

    const int ar  = tid >> 2;
    const int ac4 = (tid & 3) << 2;
    const int br  = tid >> 5;
    const int bc  = (tid & 31) << 2;

    const int nk = K >> 4;
    const bool bcol_ok = (n0 + bc) < N;

    {
        float4 a0 = *(const float4*)(A + (size_t)(m0 + ar)      * K + ac4);
        float4 a1 = *(const float4*)(A + (size_t)(m0 + ar + 64) * K + ac4);
        As[0][ac4+0][ar]    = a0.x; As[0][ac4+1][ar]    = a0.y;
        As[0][ac4+2][ar]    = a0.z; As[0][ac4+3][ar]    = a0.w;
        As[0][ac4+0][ar+64] = a1.x; As[0][ac4+1][ar+64] = a1.y;
        As[0][ac4+2][ar+64] = a1.z; As[0][ac4+3][ar+64] = a1.w;
        float4 b0 = bcol_ok ? *(const float4*)(B + (size_t)br     * N + n0 + bc)
                            : make_float4(0.f,0.f,0.f,0.f);
        float4 b1 = bcol_ok ? *(const float4*)(B + (size_t)(br+8) * N + n0 + bc)
                            : make_float4(0.f,0.f,0.f,0.f);
        *(float4*)&Bs[0][br][bc]   = b0;
        *(float4*)&Bs[0][br+8][bc] = b1;
    }
    __syncthreads();

    float acc[8][8] = {};

    for (int kt = 0; kt < nk; kt++) {
        const int buf = kt & 1;
        const int nxt = buf ^ 1;
        const bool has_next = (kt + 1) < nk;

        float4 pa0, pa1, pb0, pb1;
        if (has_next) {
            const int k0 = (kt + 1) << 4;
            pa0 = *(const float4*)(A + (size_t)(m0 + ar)      * K + k0 + ac4);
            pa1 = *(const float4*)(A + (size_t)(m0 + ar + 64) * K + k0 + ac4);
            pb0 = bcol_ok ? *(const float4*)(B + (size_t)(k0 + br)     * N + n0 + bc)
                          : make_float4(0.f,0.f,0.f,0.f);
            pb1 = bcol_ok ? *(const float4*)(B + (size_t)(k0 + br + 8) * N + n0 + bc)
                          : make_float4(0.f,0.f,0.f,0.f);
        }

#pragma unroll
        for (int kk = 0; kk < 16; kk++) {
            float a[8], b[8];
            *(float4*)&a[0] = *(const float4*)&As[buf][kk][ty*8];
            *(float4*)&a[4] = *(const float4*)&As[buf][kk][ty*8 + 4];
            *(float4*)&b[0] = *(const float4*)&Bs[buf][kk][tx*8];
            *(float4*)&b[4] = *(const float4*)&Bs[buf][kk][tx*8 + 4];
#pragma unroll
            for (int i = 0; i < 8; i++)
#pragma unroll
                for (int j = 0; j < 8; j++)
                    acc[i][j] = fmaf(a[i], b[j], acc[i][j]);
        }

        if (has_next) {
            As[nxt][ac4+0][ar]    = pa0.x; As[nxt][ac4+1][ar]    = pa0.y;
            As[nxt][ac4+2][ar]    = pa0.z; As[nxt][ac4+3][ar]    = pa0.w;
            As[nxt][ac4+0][ar+64] = pa1.x; As[nxt][ac4+1][ar+64] = pa1.y;
            As[nxt][ac4+2][ar+64] = pa1.z; As[nxt][ac4+3][ar+64] = pa1.w;
            *(float4*)&Bs[nxt][br][bc]   = pb0;
            *(float4*)&Bs[nxt][br+8][bc] = pb1;
        }
        __syncthreads();
    }

#pragma unroll
    for (int i = 0; i < 8; i++) {
        const int row = m0 + ty*8 + i;
#pragma unroll
        for (int j4 = 0; j4 < 2; j4++) {
            const int col = n0 + tx*8 + j4*4;
            if (col < N) {
                float4 bv = *(const float4*)(bias + col);
                float o0 = acc[i][j4*4+0] + bv.x;
                float o1 = acc[i][j4*4+1] + bv.y;
                float o2 = acc[i][j4*4+2] + bv.z;
                float o3 = acc[i][j4*4+3] + bv.w;
                OutT* cp = C + (size_t)row * N + col;
                cp[0] = (OutT)o0; cp[1] = (OutT)o1;
                cp[2] = (OutT)o2; cp[3] = (OutT)o3;
            }
        }
    }
}

// ---------------- transpose fp32 -> fp16: dst[c][r] = (half)src[r][c] -------
__global__ void transpose_f16(const float* __restrict__ src,
                              __half* __restrict__ dst,
                              int R, int ldsrc)
{
    __shared__ float tile[32][33];
    const int r0 = blockIdx.y * 32, c0 = blockIdx.x * 32;
    for (int i = threadIdx.y; i < 32; i += 8)
        tile[i][threadIdx.x] = src[(size_t)(r0 + i) * ldsrc + c0 + threadIdx.x];
    __syncthreads();
    for (int i = threadIdx.y; i < 32; i += 8)
        dst[(size_t)(c0 + i) * R + r0 + threadIdx.x] =
            __float2half(tile[threadIdx.x][i]);
}

// ---------------- fp32 -> fp16 bulk convert ---------------------------------
__global__ void f32_to_f16(const float* __restrict__ src,
                           __half* __restrict__ dst, int n4)
{
    int i = blockIdx.x * blockDim.x + threadIdx.x;
    if (i < n4) {
        float4 v = ((const float4*)src)[i];
        __half2 h0 = __floats2half2_rn(v.x, v.y);
        __half2 h1 = __floats2half2_rn(v.z, v.w);
        ((__half2*)dst)[2*i]   = h0;
        ((__half2*)dst)[2*i+1] = h1;
    }
}

// ---------------- embedding gather ------------------------------------------
__global__ void gather_emb(const int* __restrict__ y, const float* __restrict__ emb,
                           float* __restrict__ out)
{
    int idx = blockIdx.x * blockDim.x + threadIdx.x;
    if (idx < NB_*TDEC_*E_) {
        int row = idx >> 8;
        int e   = idx & 255;
        out[idx] = emb[(size_t)y[row] * E_ + e];
    }
}

// ---------------- skinny GEMM (fp16 B): part[kz][n][j] = sum_k A[n][k]*Bt[j][k]
// A: [32][1024] fp32, optionally the sum of NPART partials (stride partStride).
template <int NPART>
__global__ __launch_bounds__(256) void gemm_skinny_h(
    const float* __restrict__ A, const __half* __restrict__ Bt,
    float* __restrict__ part, int NBcols)
{
    __shared__ float As[256][36];
    const int j0 = blockIdx.x * 32;
    const int kz = blockIdx.y;
    const int kbase = kz * 256;
    const int tid = threadIdx.x;

#pragma unroll 4
    for (int i = 0; i < 32; i++) {
        float s = A[(size_t)i * 1024 + kbase + tid];
#pragma unroll
        for (int p = 1; p < NPART; p++)
            s += A[(size_t)p * (NB_*D_) + (size_t)i * 1024 + kbase + tid];
        As[tid][i] = s;
    }
    __syncthreads();

    const int tx = tid & 31, ty = tid >> 5;
    const int j = j0 + tx;
    const uint4* bp = (const uint4*)(Bt + (size_t)j * 1024 + kbase);

    float acc0 = 0.f, acc1 = 0.f, acc2 = 0.f, acc3 = 0.f;
#pragma unroll 4
    for (int kk = 0; kk < 256; kk += 8) {
        uint4 u = bp[kk >> 3];
        const __half2* hp = (const __half2*)&u;
        float b[8];
        float2 f0 = __half22float2(hp[0]); b[0] = f0.x; b[1] = f0.y;
        float2 f1 = __half22float2(hp[1]); b[2] = f1.x; b[3] = f1.y;
        float2 f2 = __half22float2(hp[2]); b[4] = f2.x; b[5] = f2.y;
        float2 f3 = __half22float2(hp[3]); b[6] = f3.x; b[7] = f3.y;
#pragma unroll
        for (int u8 = 0; u8 < 8; u8++) {
            float4 a = *(const float4*)&As[kk + u8][ty * 4];
            acc0 = fmaf(b[u8], a.x, acc0);
            acc1 = fmaf(b[u8], a.y, acc1);
            acc2 = fmaf(b[u8], a.z, acc2);
            acc3 = fmaf(b[u8], a.w, acc3);
        }
    }
    const int n = ty * 4;
    float* po = part + (size_t)(kz * 32 + n) * NBcols + j;
    po[0]                 = acc0;
    po[(size_t)NBcols]    = acc1;
    po[(size_t)2*NBcols]  = acc2;
    po[(size_t)3*NBcols]  = acc3;
}

// ---------------- score: s[n][t] = v . tanh(keys[n][t] + q[n]) + bv ---------
__global__ __launch_bounds__(256) void score_kernel(
    const float* __restrict__ b2, const float* __restrict__ v,
    const float* __restrict__ bv)
{
    __shared__ float qs[DM_];
    __shared__ float vs[DM_];
    const int n = blockIdx.y;
    const int tbase = blockIdx.x * 20;
    const int tid = threadIdx.x;

    for (int d = tid; d < DM_; d += 256) {
        float s = b2[d];
#pragma unroll
        for (int sp = 0; sp < 4; sp++) s += g_qpart[sp*NB_*DM_ + n*DM_ + d];
        qs[d] = s;
        vs[d] = v[d];
    }
    __syncthreads();

    const int w = tid >> 5, lane = tid & 31;
    const float bvv = bv[0];
    for (int t = tbase + w; t < tbase + 20; t += 8) {
        const uint4* kp = (const uint4*)(g_keysh + ((size_t)(n*TENC_ + t) << 10));
        float acc = 0.f;
#pragma unroll
        for (int i = 0; i < 4; i++) {
            uint4 u = kp[lane + (i << 5)];
            const __half2* hp = (const __half2*)&u;
            const int d0 = (lane + (i << 5)) << 3;
            float4 q1 = *(const float4*)&qs[d0];
            float4 q2 = *(const float4*)&qs[d0 + 4];
            float4 v1 = *(const float4*)&vs[d0];
            float4 v2 = *(const float4*)&vs[d0 + 4];
            float2 f0 = __half22float2(hp[0]);
            float2 f1 = __half22float2(hp[1]);
            float2 f2 = __half22float2(hp[2]);
            float2 f3 = __half22float2(hp[3]);
            acc = fmaf(tanh_approx(f0.x + q1.x), v1.x, acc);
            acc = fmaf(tanh_approx(f0.y + q1.y), v1.y, acc);
            acc = fmaf(tanh_approx(f1.x + q1.z), v1.z, acc);
            acc = fmaf(tanh_approx(f1.y + q1.w), v1.w, acc);
            acc = fmaf(tanh_approx(f2.x + q2.x), v2.x, acc);
            acc = fmaf(tanh_approx(f2.y + q2.y), v2.y, acc);
            acc = fmaf(tanh_approx(f3.x + q2.z), v2.z, acc);
            acc = fmaf(tanh_approx(f3.y + q2.w), v2.w, acc);
        }
#pragma unroll
        for (int off = 16; off; off >>= 1)
            acc += __shfl_xor_sync(0xffffffffu, acc, off);
        if (lane == 0) g_scores[n*TENC_ + t] = acc + bvv;
    }
}

// ---------------- softmax (redundant per block) + partial context -----------
// grid (4 d-chunks, 4 t-chunks, 32 n). Each block sums its 125-t slice.
__global__ __launch_bounds__(256) void context_part(void)
{
    __shared__ float ws[TENC_];
    __shared__ float red[256];
    const int n  = blockIdx.z;
    const int tc = blockIdx.y;
    const int d0 = blockIdx.x * 256;
    const int tid = threadIdx.x;

    float mx = -1e30f;
    for (int t = tid; t < TENC_; t += 256) {
        float s = g_scores[n*TENC_ + t];
        ws[t] = s;
        mx = fmaxf(mx, s);
    }
    red[tid] = mx; __syncthreads();
    for (int s = 128; s; s >>= 1) {
        if (tid < s) red[tid] = fmaxf(red[tid], red[tid+s]);
        __syncthreads();
    }
    mx = red[0];
    __syncthreads();
    float lsum = 0.f;
    for (int t = tid; t < TENC_; t += 256) {
        float e = __expf(ws[t] - mx);
        ws[t] = e;
        lsum += e;
    }
    red[tid] = lsum; __syncthreads();
    for (int s = 128; s; s >>= 1) {
        if (tid < s) red[tid] += red[tid+s];
        __syncthreads();
    }
    const float inv = 1.f / red[0];

    const __half* xp = g_xh + (size_t)n * TENC_ * D_ + d0 + tid;
    const int t0 = tc * 125;
    float a[5];
#pragma unroll
    for (int u = 0; u < 5; u++) a[u] = 0.f;
    for (int t = t0; t < t0 + 125; t += 5) {   // 125 = 25*5
#pragma unroll
        for (int u = 0; u < 5; u++)
            a[u] = fmaf(ws[t+u], __half2float(xp[(size_t)(t+u) << 10]), a[u]);
    }
    g_ctxpart[((size_t)tc * NB_ + n) * D_ + d0 + tid] =
        (((a[0]+a[1]) + (a[2]+a[3])) + a[4]) * inv;
}

// ---------------- GRU gates (h_prev == 0: Uh unused, only b_rec) ------------
__global__ __launch_bounds__(256) void gate_kernel(const float* __restrict__ b_rec, int t)
{
    int gid = blockIdx.x * blockDim.x + threadIdx.x;
    if (gid >= NB_*DM_) return;
    const int n = gid >> 10, j = gid & 1023;

    float xz = 0.f, xr = 0.f, xh = 0.f;
#pragma unroll
    for (int s = 0; s < 4; s++) {
        const float* p = g_gxpart + (size_t)s*NB_*G3_ + (size_t)n*G3_;
        xz += p[j]; xr += p[j+1024]; xh += p[j+2048];
    }
    const float* ge = g_gxemb + (size_t)(n*TDEC_ + t) * G3_;
    xz += ge[j]; xr += ge[j+1024]; xh += ge[j+2048];

    float z  = 1.f / (1.f + __expf(-(xz + b_rec[j])));
    float r  = 1.f / (1.f + __expf(-(xr + b_rec[j+1024])));
    float hh = tanhf(xh + r * b_rec[j+2048]);
    float h  = (1.f - z) * hh;

    g_h[gid] = h;
    g_H[(size_t)(n*TDEC_ + t) * DM_ + j] = h;
}

// ---------------- launch -----------------------------------------------------
extern "C" void kernel_launch(void* const* d_in, const int* in_sizes, int n_in,
                              void* d_out, int out_size)
{
    (void)in_sizes; (void)n_in; (void)out_size;
    const float* x    = (const float*)d_in[0];
    const float* m    = (const float*)d_in[1];
    const int*   y    = (const int*)  d_in[2];
    const float* emb  = (const float*)d_in[3];
    const float* W1   = (const float*)d_in[4];
    const float* b1   = (const float*)d_in[5];
    const float* W2   = (const float*)d_in[6];
    const float* b2   = (const float*)d_in[7];
    const float* v    = (const float*)d_in[8];
    const float* bv   = (const float*)d_in[9];
    const float* Wx   = (const float*)d_in[10];
    // d_in[11] = Uh — provably unused (h_prev == 0)
    const float* b_in = (const float*)d_in[12];
    const float* b_rec= (const float*)d_in[13];
    const float* Wo   = (const float*)d_in[14];
    const float* bo   = (const float*)d_in[15];
    float* out = (float*)d_out;

    __half *keysh, *xh, *W2t, *Wxt;
    float *yemb, *gxemb, *qpart, *ctxpart, *gxpart, *h, *H;
    cudaGetSymbolAddress((void**)&keysh,  g_keysh);
    cudaGetSymbolAddress((void**)&xh,     g_xh);
    cudaGetSymbolAddress((void**)&W2t,    g_W2t);
    cudaGetSymbolAddress((void**)&Wxt,    g_Wxt);
    cudaGetSymbolAddress((void**)&yemb,   g_yemb);
    cudaGetSymbolAddress((void**)&gxemb,  g_gxemb);
    cudaGetSymbolAddress((void**)&qpart,  g_qpart);
    cudaGetSymbolAddress((void**)&ctxpart,g_ctxpart);
    cudaGetSymbolAddress((void**)&gxpart, g_gxpart);
    cudaGetSymbolAddress((void**)&h,      g_h);
    cudaGetSymbolAddress((void**)&H,      g_H);

    // ---- step-invariant precompute ----
    gather_emb<<<(NB_*TDEC_*E_ + 255)/256, 256>>>(y, emb, yemb);
    // keys(fp16) = x @ W1 + b1 : [16000,1024] @ [1024,1024]
    sgemm128<__half><<<dim3(16000/128, 1024/128), 256>>>(x, W1, b1, keysh,
                                                         16000, 1024, 1024);
    // gxemb = yemb @ Wx[1024:1280,:] + b_in
    sgemm128<float><<<dim3(3200/128, 3072/128), 256>>>(yemb, Wx + (size_t)1024*G3_,
                                                       b_in, gxemb, 3200, 3072, 256);
    // fp16 transposed weights + fp16 x copy
    transpose_f16<<<dim3(1024/32, 1024/32), dim3(32,8)>>>(W2, W2t, 1024, 1024);
    transpose_f16<<<dim3(3072/32, 1024/32), dim3(32,8)>>>(Wx, Wxt, 1024, 3072);
    f32_to_f16<<<(NB_*TENC_*D_/4 + 255)/256, 256>>>(x, xh, NB_*TENC_*D_/4);
    cudaMemcpyAsync(h, m, (size_t)NB_*DM_*sizeof(float), cudaMemcpyDeviceToDevice);

    // ---- sequential decode loop ----
    for (int t = 0; t < TDEC_; t++) {
        gemm_skinny_h<1><<<dim3(DM_/32, 4), 256>>>(h, W2t, qpart, DM_);
        score_kernel<<<dim3(TENC_/20, NB_), 256>>>(b2, v, bv);
        context_part<<<dim3(4, 4, NB_), 256>>>();
        gemm_skinny_h<4><<<dim3(G3_/32, 4), 256>>>(ctxpart, Wxt, gxpart, G3_);
        gate_kernel<<<NB_*DM_/256, 256>>>(b_rec, t);
    }

    // ---- out = H @ Wo + bo : [3200,1024] @ [1024,8000] ----
    sgemm128<float><<<dim3(3200/128, (8000 + 127)/128), 256>>>(H, Wo, bo, out,
                                                               3200, 8000, 1024);
}

// round 6
// speedup vs baseline: 2.4110x; 1.1476x over previous
#include <cuda_runtime.h>
#include <cuda_fp16.h>
#include <cuda_bf16.h>
#include <cstdint>

#define NB_   32
#define TENC_ 500
#define D_    1024
#define DM_   1024
#define TDEC_ 100
#define E_    256
#define C_    8000
#define G3_   (3*DM_)   // 3072

// ---------------- scratch (device globals; no allocations allowed) ----------
__device__ __half g_keysh[NB_*TENC_*DM_];    // 32.8 MB fp16
__device__ __half g_xh[NB_*TENC_*D_];        // 32.8 MB fp16 copy of x
__device__ __half g_W2t[DM_*DM_];            // W2^T fp16 [j][k]
__device__ __half g_Wxt[G3_*DM_];            // Wx^T (context rows) fp16 [j][k]
__device__ float g_yemb[NB_*TDEC_*E_];
__device__ float g_gxemb[NB_*TDEC_*G3_];     // 39.3 MB
__device__ float g_qpart[4*NB_*DM_];
__device__ float g_scores[NB_*TENC_];
__device__ float g_ctxpart[4*NB_*D_];
__device__ float g_gxpart[4*NB_*G3_];
__device__ float g_h[NB_*DM_];
__device__ float g_H[NB_*TDEC_*DM_];         // 13.1 MB
// split-bf16 staging for tensor-core GEMMs
__device__ __nv_bfloat16 g_Ah[16000*1024];   // 32.8 MB
__device__ __nv_bfloat16 g_Al[16000*1024];   // 32.8 MB
__device__ __nv_bfloat16 g_Bh[1024*8000];    // 16.4 MB
__device__ __nv_bfloat16 g_Bl[1024*8000];    // 16.4 MB

__device__ __forceinline__ float tanh_approx(float x) {
    float y;
    asm("tanh.approx.f32 %0, %1;" : "=f"(y) : "f"(x));
    return y;
}

// ---------------- tensor-core primitives ------------------------------------
__device__ __forceinline__ void ldsm4(uint32_t* r, uint32_t addr) {
    asm volatile("ldmatrix.sync.aligned.m8n8.x4.shared.b16 {%0,%1,%2,%3}, [%4];"
        : "=r"(r[0]), "=r"(r[1]), "=r"(r[2]), "=r"(r[3]) : "r"(addr));
}
__device__ __forceinline__ void ldsm4t(uint32_t* r, uint32_t addr) {
    asm volatile("ldmatrix.sync.aligned.m8n8.x4.trans.shared.b16 {%0,%1,%2,%3}, [%4];"
        : "=r"(r[0]), "=r"(r[1]), "=r"(r[2]), "=r"(r[3]) : "r"(addr));
}
__device__ __forceinline__ void mma16816(float* c, const uint32_t* a, const uint32_t* b) {
    asm volatile("mma.sync.aligned.m16n8k16.row.col.f32.bf16.bf16.f32 "
        "{%0,%1,%2,%3},{%4,%5,%6,%7},{%8,%9},{%0,%1,%2,%3};"
        : "+f"(c[0]), "+f"(c[1]), "+f"(c[2]), "+f"(c[3])
        : "r"(a[0]), "r"(a[1]), "r"(a[2]), "r"(a[3]), "r"(b[0]), "r"(b[1]));
}

// ---------------- split fp32 -> (bf16 hi, bf16 lo) ---------------------------
__global__ void split_bf16(const float* __restrict__ src,
                           __nv_bfloat16* __restrict__ hi,
                           __nv_bfloat16* __restrict__ lo, int n4)
{
    int i = blockIdx.x * blockDim.x + threadIdx.x;
    if (i < n4) {
        float4 v = ((const float4*)src)[i];
        __nv_bfloat16 h0 = __float2bfloat16(v.x);
        __nv_bfloat16 h1 = __float2bfloat16(v.y);
        __nv_bfloat16 h2 = __float2bfloat16(v.z);
        __nv_bfloat16 h3 = __float2bfloat16(v.w);
        __nv_bfloat162 hh0; hh0.x = h0; hh0.y = h1;
        __nv_bfloat162 hh1; hh1.x = h2; hh1.y = h3;
        ((__nv_bfloat162*)hi)[2*i]   = hh0;
        ((__nv_bfloat162*)hi)[2*i+1] = hh1;
        __nv_bfloat162 ll0, ll1;
        ll0.x = __float2bfloat16(v.x - __bfloat162float(h0));
        ll0.y = __float2bfloat16(v.y - __bfloat162float(h1));
        ll1.x = __float2bfloat16(v.z - __bfloat162float(h2));
        ll1.y = __float2bfloat16(v.w - __bfloat162float(h3));
        ((__nv_bfloat162*)lo)[2*i]   = ll0;
        ((__nv_bfloat162*)lo)[2*i+1] = ll1;
    }
}

// ---------------- split-bf16 tensor-core GEMM --------------------------------
// C[M,N] = (Ah+Al)[M,K] @ (Bh+Bl)[K,N] + bias  (drops Al*Bl, ~2^-18)
// 128x128 tile, BK=32, 256 threads (8 warps, 2x4), warp tile 64x32.
// M%128==0, K%32==0; N boundary guarded (N%8==0 required).
template <typename OutT>
__global__ __launch_bounds__(256) void hgemm_split(
    const __nv_bfloat16* __restrict__ Ah, const __nv_bfloat16* __restrict__ Al,
    const __nv_bfloat16* __restrict__ Bh, const __nv_bfloat16* __restrict__ Bl,
    const float* __restrict__ bias, OutT* __restrict__ C,
    int M, int N, int K)
{
    __shared__ __nv_bfloat16 Ash[128][40];
    __shared__ __nv_bfloat16 Asl[128][40];
    __shared__ __nv_bfloat16 Bsh[32][136];
    __shared__ __nv_bfloat16 Bsl[32][136];

    const int m0 = blockIdx.x * 128;
    const int n0 = blockIdx.y * 128;
    const int tid = threadIdx.x;
    const int wid = tid >> 5, lane = tid & 31;
    const int wm = wid >> 2, wn = wid & 3;

    float acc[4][4][4] = {};

    const int arow = tid >> 2;            // 0..63
    const int acol = (tid & 3) * 8;       // 0,8,16,24
    const int bk   = tid >> 4;            // 0..15
    const int bcol = (tid & 15) * 8;      // 0..120
    const bool bok = (n0 + bcol) < N;     // N%8==0 -> whole 16B chunk valid

    const uint32_t as_h = (uint32_t)__cvta_generic_to_shared(&Ash[0][0]);
    const uint32_t as_l = (uint32_t)__cvta_generic_to_shared(&Asl[0][0]);
    const uint32_t bs_h = (uint32_t)__cvta_generic_to_shared(&Bsh[0][0]);
    const uint32_t bs_l = (uint32_t)__cvta_generic_to_shared(&Bsl[0][0]);

    const uint4 z4 = make_uint4(0u, 0u, 0u, 0u);

    for (int k0 = 0; k0 < K; k0 += 32) {
        __syncthreads();
        *(uint4*)&Ash[arow][acol] =
            *(const uint4*)(Ah + (size_t)(m0 + arow) * K + k0 + acol);
        *(uint4*)&Ash[arow+64][acol] =
            *(const uint4*)(Ah + (size_t)(m0 + arow + 64) * K + k0 + acol);
        *(uint4*)&Asl[arow][acol] =
            *(const uint4*)(Al + (size_t)(m0 + arow) * K + k0 + acol);
        *(uint4*)&Asl[arow+64][acol] =
            *(const uint4*)(Al + (size_t)(m0 + arow + 64) * K + k0 + acol);
        *(uint4*)&Bsh[bk][bcol] =
            bok ? *(const uint4*)(Bh + (size_t)(k0 + bk) * N + n0 + bcol) : z4;
        *(uint4*)&Bsh[bk+16][bcol] =
            bok ? *(const uint4*)(Bh + (size_t)(k0 + bk + 16) * N + n0 + bcol) : z4;
        *(uint4*)&Bsl[bk][bcol] =
            bok ? *(const uint4*)(Bl + (size_t)(k0 + bk) * N + n0 + bcol) : z4;
        *(uint4*)&Bsl[bk+16][bcol] =
            bok ? *(const uint4*)(Bl + (size_t)(k0 + bk + 16) * N + n0 + bcol) : z4;
        __syncthreads();

#pragma unroll
        for (int kk = 0; kk < 32; kk += 16) {
            uint32_t ah[4][4], al[4][4], bh[4][2], bl[4][2];
#pragma unroll
            for (int mt = 0; mt < 4; mt++) {
                const uint32_t off =
                    (uint32_t)(((wm*64 + mt*16 + (lane & 15)) * 40
                                + kk + ((lane >> 4) << 3)) << 1);
                ldsm4(ah[mt], as_h + off);
                ldsm4(al[mt], as_l + off);
            }
#pragma unroll
            for (int ng = 0; ng < 2; ng++) {
                const uint32_t off =
                    (uint32_t)((((kk + (lane & 15)) * 136)
                                + wn*32 + ng*16 + ((lane >> 4) << 3)) << 1);
                uint32_t r[4];
                ldsm4t(r, bs_h + off);
                bh[2*ng][0] = r[0]; bh[2*ng][1] = r[1];
                bh[2*ng+1][0] = r[2]; bh[2*ng+1][1] = r[3];
                ldsm4t(r, bs_l + off);
                bl[2*ng][0] = r[0]; bl[2*ng][1] = r[1];
                bl[2*ng+1][0] = r[2]; bl[2*ng+1][1] = r[3];
            }
#pragma unroll
            for (int mt = 0; mt < 4; mt++)
#pragma unroll
                for (int nt = 0; nt < 4; nt++) {
                    mma16816(acc[mt][nt], ah[mt], bh[nt]);
                    mma16816(acc[mt][nt], ah[mt], bl[nt]);
                    mma16816(acc[mt][nt], al[mt], bh[nt]);
                }
        }
    }

    const int tr = lane >> 2;
    const int tc = (lane & 3) * 2;
#pragma unroll
    for (int mt = 0; mt < 4; mt++) {
#pragma unroll
        for (int nt = 0; nt < 4; nt++) {
            const int col = n0 + wn*32 + nt*8 + tc;
            if (col < N) {
                const float b0 = bias[col], b1 = bias[col+1];
                const int r0 = m0 + wm*64 + mt*16 + tr;
                OutT* p0 = C + (size_t)r0 * N + col;
                OutT* p1 = C + (size_t)(r0 + 8) * N + col;
                p0[0] = (OutT)(acc[mt][nt][0] + b0);
                p0[1] = (OutT)(acc[mt][nt][1] + b1);
                p1[0] = (OutT)(acc[mt][nt][2] + b0);
                p1[1] = (OutT)(acc[mt][nt][3] + b1);
            }
        }
    }
}

// ---------------- transpose fp32 -> fp16: dst[c][r] = (half)src[r][c] -------
__global__ void transpose_f16(const float* __restrict__ src,
                              __half* __restrict__ dst,
                              int R, int ldsrc)
{
    __shared__ float tile[32][33];
    const int r0 = blockIdx.y * 32, c0 = blockIdx.x * 32;
    for (int i = threadIdx.y; i < 32; i += 8)
        tile[i][threadIdx.x] = src[(size_t)(r0 + i) * ldsrc + c0 + threadIdx.x];
    __syncthreads();
    for (int i = threadIdx.y; i < 32; i += 8)
        dst[(size_t)(c0 + i) * R + r0 + threadIdx.x] =
            __float2half(tile[threadIdx.x][i]);
}

// ---------------- fp32 -> fp16 bulk convert ---------------------------------
__global__ void f32_to_f16(const float* __restrict__ src,
                           __half* __restrict__ dst, int n4)
{
    int i = blockIdx.x * blockDim.x + threadIdx.x;
    if (i < n4) {
        float4 v = ((const float4*)src)[i];
        ((__half2*)dst)[2*i]   = __floats2half2_rn(v.x, v.y);
        ((__half2*)dst)[2*i+1] = __floats2half2_rn(v.z, v.w);
    }
}

// ---------------- embedding gather ------------------------------------------
__global__ void gather_emb(const int* __restrict__ y, const float* __restrict__ emb,
                           float* __restrict__ out)
{
    int idx = blockIdx.x * blockDim.x + threadIdx.x;
    if (idx < NB_*TDEC_*E_) {
        int row = idx >> 8;
        int e   = idx & 255;
        out[idx] = emb[(size_t)y[row] * E_ + e];
    }
}

// ---------------- skinny GEMM (fp16 B) ---------------------------------------
template <int NPART>
__global__ __launch_bounds__(256) void gemm_skinny_h(
    const float* __restrict__ A, const __half* __restrict__ Bt,
    float* __restrict__ part, int NBcols)
{
    __shared__ float As[256][36];
    const int j0 = blockIdx.x * 32;
    const int kz = blockIdx.y;
    const int kbase = kz * 256;
    const int tid = threadIdx.x;

#pragma unroll 4
    for (int i = 0; i < 32; i++) {
        float s = A[(size_t)i * 1024 + kbase + tid];
#pragma unroll
        for (int p = 1; p < NPART; p++)
            s += A[(size_t)p * (NB_*D_) + (size_t)i * 1024 + kbase + tid];
        As[tid][i] = s;
    }
    __syncthreads();

    const int tx = tid & 31, ty = tid >> 5;
    const int j = j0 + tx;
    const uint4* bp = (const uint4*)(Bt + (size_t)j * 1024 + kbase);

    float acc0 = 0.f, acc1 = 0.f, acc2 = 0.f, acc3 = 0.f;
#pragma unroll 4
    for (int kk = 0; kk < 256; kk += 8) {
        uint4 u = bp[kk >> 3];
        const __half2* hp = (const __half2*)&u;
        float b[8];
        float2 f0 = __half22float2(hp[0]); b[0] = f0.x; b[1] = f0.y;
        float2 f1 = __half22float2(hp[1]); b[2] = f1.x; b[3] = f1.y;
        float2 f2 = __half22float2(hp[2]); b[4] = f2.x; b[5] = f2.y;
        float2 f3 = __half22float2(hp[3]); b[6] = f3.x; b[7] = f3.y;
#pragma unroll
        for (int u8 = 0; u8 < 8; u8++) {
            float4 a = *(const float4*)&As[kk + u8][ty * 4];
            acc0 = fmaf(b[u8], a.x, acc0);
            acc1 = fmaf(b[u8], a.y, acc1);
            acc2 = fmaf(b[u8], a.z, acc2);
            acc3 = fmaf(b[u8], a.w, acc3);
        }
    }
    const int n = ty * 4;
    float* po = part + (size_t)(kz * 32 + n) * NBcols + j;
    po[0]                 = acc0;
    po[(size_t)NBcols]    = acc1;
    po[(size_t)2*NBcols]  = acc2;
    po[(size_t)3*NBcols]  = acc3;
}

// ---------------- score: s[n][t] = v . tanh(keys[n][t] + q[n]) + bv ---------
__global__ __launch_bounds__(256) void score_kernel(
    const float* __restrict__ b2, const float* __restrict__ v,
    const float* __restrict__ bv)
{
    __shared__ float qs[DM_];
    __shared__ float vs[DM_];
    const int n = blockIdx.y;
    const int tbase = blockIdx.x * 20;
    const int tid = threadIdx.x;

    for (int d = tid; d < DM_; d += 256) {
        float s = b2[d];
#pragma unroll
        for (int sp = 0; sp < 4; sp++) s += g_qpart[sp*NB_*DM_ + n*DM_ + d];
        qs[d] = s;
        vs[d] = v[d];
    }
    __syncthreads();

    const int w = tid >> 5, lane = tid & 31;
    const float bvv = bv[0];
    for (int t = tbase + w; t < tbase + 20; t += 8) {
        const uint4* kp = (const uint4*)(g_keysh + ((size_t)(n*TENC_ + t) << 10));
        float acc = 0.f;
#pragma unroll
        for (int i = 0; i < 4; i++) {
            uint4 u = kp[lane + (i << 5)];
            const __half2* hp = (const __half2*)&u;
            const int d0 = (lane + (i << 5)) << 3;
            float4 q1 = *(const float4*)&qs[d0];
            float4 q2 = *(const float4*)&qs[d0 + 4];
            float4 v1 = *(const float4*)&vs[d0];
            float4 v2 = *(const float4*)&vs[d0 + 4];
            float2 f0 = __half22float2(hp[0]);
            float2 f1 = __half22float2(hp[1]);
            float2 f2 = __half22float2(hp[2]);
            float2 f3 = __half22float2(hp[3]);
            acc = fmaf(tanh_approx(f0.x + q1.x), v1.x, acc);
            acc = fmaf(tanh_approx(f0.y + q1.y), v1.y, acc);
            acc = fmaf(tanh_approx(f1.x + q1.z), v1.z, acc);
            acc = fmaf(tanh_approx(f1.y + q1.w), v1.w, acc);
            acc = fmaf(tanh_approx(f2.x + q2.x), v2.x, acc);
            acc = fmaf(tanh_approx(f2.y + q2.y), v2.y, acc);
            acc = fmaf(tanh_approx(f3.x + q2.z), v2.z, acc);
            acc = fmaf(tanh_approx(f3.y + q2.w), v2.w, acc);
        }
#pragma unroll
        for (int off = 16; off; off >>= 1)
            acc += __shfl_xor_sync(0xffffffffu, acc, off);
        if (lane == 0) g_scores[n*TENC_ + t] = acc + bvv;
    }
}

// ---------------- softmax (redundant per block) + partial context -----------
__global__ __launch_bounds__(256) void context_part(void)
{
    __shared__ float ws[TENC_];
    __shared__ float red[256];
    const int n  = blockIdx.z;
    const int tc = blockIdx.y;
    const int d0 = blockIdx.x * 256;
    const int tid = threadIdx.x;

    float mx = -1e30f;
    for (int t = tid; t < TENC_; t += 256) {
        float s = g_scores[n*TENC_ + t];
        ws[t] = s;
        mx = fmaxf(mx, s);
    }
    red[tid] = mx; __syncthreads();
    for (int s = 128; s; s >>= 1) {
        if (tid < s) red[tid] = fmaxf(red[tid], red[tid+s]);
        __syncthreads();
    }
    mx = red[0];
    __syncthreads();
    float lsum = 0.f;
    for (int t = tid; t < TENC_; t += 256) {
        float e = __expf(ws[t] - mx);
        ws[t] = e;
        lsum += e;
    }
    red[tid] = lsum; __syncthreads();
    for (int s = 128; s; s >>= 1) {
        if (tid < s) red[tid] += red[tid+s];
        __syncthreads();
    }
    const float inv = 1.f / red[0];

    const __half* xp = g_xh + (size_t)n * TENC_ * D_ + d0 + tid;
    const int t0 = tc * 125;
    float a[5];
#pragma unroll
    for (int u = 0; u < 5; u++) a[u] = 0.f;
    for (int t = t0; t < t0 + 125; t += 5) {
#pragma unroll
        for (int u = 0; u < 5; u++)
            a[u] = fmaf(ws[t+u], __half2float(xp[(size_t)(t+u) << 10]), a[u]);
    }
    g_ctxpart[((size_t)tc * NB_ + n) * D_ + d0 + tid] =
        (((a[0]+a[1]) + (a[2]+a[3])) + a[4]) * inv;
}

// ---------------- GRU gates (h_prev == 0: Uh unused, only b_rec) ------------
__global__ __launch_bounds__(256) void gate_kernel(const float* __restrict__ b_rec, int t)
{
    int gid = blockIdx.x * blockDim.x + threadIdx.x;
    if (gid >= NB_*DM_) return;
    const int n = gid >> 10, j = gid & 1023;

    float xz = 0.f, xr = 0.f, xh = 0.f;
#pragma unroll
    for (int s = 0; s < 4; s++) {
        const float* p = g_gxpart + (size_t)s*NB_*G3_ + (size_t)n*G3_;
        xz += p[j]; xr += p[j+1024]; xh += p[j+2048];
    }
    const float* ge = g_gxemb + (size_t)(n*TDEC_ + t) * G3_;
    xz += ge[j]; xr += ge[j+1024]; xh += ge[j+2048];

    float z  = 1.f / (1.f + __expf(-(xz + b_rec[j])));
    float r  = 1.f / (1.f + __expf(-(xr + b_rec[j+1024])));
    float hh = tanhf(xh + r * b_rec[j+2048]);
    float h  = (1.f - z) * hh;

    g_h[gid] = h;
    g_H[(size_t)(n*TDEC_ + t) * DM_ + j] = h;
}

// ---------------- launch -----------------------------------------------------
extern "C" void kernel_launch(void* const* d_in, const int* in_sizes, int n_in,
                              void* d_out, int out_size)
{
    (void)in_sizes; (void)n_in; (void)out_size;
    const float* x    = (const float*)d_in[0];
    const float* m    = (const float*)d_in[1];
    const int*   y    = (const int*)  d_in[2];
    const float* emb  = (const float*)d_in[3];
    const float* W1   = (const float*)d_in[4];
    const float* b1   = (const float*)d_in[5];
    const float* W2   = (const float*)d_in[6];
    const float* b2   = (const float*)d_in[7];
    const float* v    = (const float*)d_in[8];
    const float* bv   = (const float*)d_in[9];
    const float* Wx   = (const float*)d_in[10];
    // d_in[11] = Uh — provably unused (h_prev == 0)
    const float* b_in = (const float*)d_in[12];
    const float* b_rec= (const float*)d_in[13];
    const float* Wo   = (const float*)d_in[14];
    const float* bo   = (const float*)d_in[15];
    float* out = (float*)d_out;

    __half *keysh, *xh, *W2t, *Wxt;
    __nv_bfloat16 *Ah, *Al, *Bh, *Bl;
    float *yemb, *gxemb, *qpart, *ctxpart, *gxpart, *h, *H;
    cudaGetSymbolAddress((void**)&keysh,  g_keysh);
    cudaGetSymbolAddress((void**)&xh,     g_xh);
    cudaGetSymbolAddress((void**)&W2t,    g_W2t);
    cudaGetSymbolAddress((void**)&Wxt,    g_Wxt);
    cudaGetSymbolAddress((void**)&yemb,   g_yemb);
    cudaGetSymbolAddress((void**)&gxemb,  g_gxemb);
    cudaGetSymbolAddress((void**)&qpart,  g_qpart);
    cudaGetSymbolAddress((void**)&ctxpart,g_ctxpart);
    cudaGetSymbolAddress((void**)&gxpart, g_gxpart);
    cudaGetSymbolAddress((void**)&h,      g_h);
    cudaGetSymbolAddress((void**)&H,      g_H);
    cudaGetSymbolAddress((void**)&Ah,     g_Ah);
    cudaGetSymbolAddress((void**)&Al,     g_Al);
    cudaGetSymbolAddress((void**)&Bh,     g_Bh);
    cudaGetSymbolAddress((void**)&Bl,     g_Bl);

    // ---- step-invariant precompute ----
    gather_emb<<<(NB_*TDEC_*E_ + 255)/256, 256>>>(y, emb, yemb);

    // keys(fp16) = x @ W1 + b1 via split-bf16 tensor cores
    split_bf16<<<(16000*1024/4 + 255)/256, 256>>>(x,  Ah, Al, 16000*1024/4);
    split_bf16<<<(1024*1024/4  + 255)/256, 256>>>(W1, Bh, Bl, 1024*1024/4);
    hgemm_split<__half><<<dim3(16000/128, 1024/128), 256>>>(
        Ah, Al, Bh, Bl, b1, keysh, 16000, 1024, 1024);

    // gxemb = yemb @ Wx[1024:1280,:] + b_in via split-bf16 tensor cores
    split_bf16<<<(3200*256/4 + 255)/256, 256>>>(yemb, Ah, Al, 3200*256/4);
    split_bf16<<<(256*3072/4 + 255)/256, 256>>>(Wx + (size_t)1024*G3_, Bh, Bl,
                                                256*3072/4);
    hgemm_split<float><<<dim3(3200/128, 3072/128), 256>>>(
        Ah, Al, Bh, Bl, b_in, gxemb, 3200, 3072, 256);

    // fp16 transposed weights + fp16 x copy for the decode loop
    transpose_f16<<<dim3(1024/32, 1024/32), dim3(32,8)>>>(W2, W2t, 1024, 1024);
    transpose_f16<<<dim3(3072/32, 1024/32), dim3(32,8)>>>(Wx, Wxt, 1024, 3072);
    f32_to_f16<<<(NB_*TENC_*D_/4 + 255)/256, 256>>>(x, xh, NB_*TENC_*D_/4);
    cudaMemcpyAsync(h, m, (size_t)NB_*DM_*sizeof(float), cudaMemcpyDeviceToDevice);

    // ---- sequential decode loop ----
    for (int t = 0; t < TDEC_; t++) {
        gemm_skinny_h<1><<<dim3(DM_/32, 4), 256>>>(h, W2t, qpart, DM_);
        score_kernel<<<dim3(TENC_/20, NB_), 256>>>(b2, v, bv);
        context_part<<<dim3(4, 4, NB_), 256>>>();
        gemm_skinny_h<4><<<dim3(G3_/32, 4), 256>>>(ctxpart, Wxt, gxpart, G3_);
        gate_kernel<<<NB_*DM_/256, 256>>>(b_rec, t);
    }

    // ---- out = H @ Wo + bo via split-bf16 tensor cores ----
    split_bf16<<<(3200*1024/4 + 255)/256, 256>>>(H,  Ah, Al, 3200*1024/4);
    split_bf16<<<(1024*8000/4 + 255)/256, 256>>>(Wo, Bh, Bl, 1024*8000/4);
    hgemm_split<float><<<dim3(3200/128, (8000 + 127)/128), 256>>>(
        Ah, Al, Bh, Bl, bo, out, 3200, 8000, 1024);
}

// round 7
// speedup vs baseline: 2.4424x; 1.0130x over previous
#include <cuda_runtime.h>
#include <cuda_fp16.h>
#include <cuda_bf16.h>
#include <cstdint>

#define NB_   32
#define TENC_ 500
#define D_    1024
#define DM_   1024
#define TDEC_ 100
#define E_    256
#define C_    8000
#define G3_   (3*DM_)   // 3072

// ---------------- scratch (device globals; no allocations allowed) ----------
__device__ __half g_keysh[NB_*TENC_*DM_];    // 32.8 MB fp16
__device__ __half g_xh[NB_*TENC_*D_];        // 32.8 MB fp16 copy of x
__device__ __half g_W2t[DM_*DM_];            // W2^T fp16 [j][k]
__device__ __half g_Wxt[G3_*DM_];            // Wx^T (context rows) fp16 [j][k]
__device__ float g_yemb[NB_*TDEC_*E_];
__device__ float g_gxemb[NB_*TDEC_*G3_];     // 39.3 MB
__device__ float g_qpart[4*NB_*DM_];
__device__ float g_scores[NB_*TENC_];
__device__ float g_ctxpart[4*NB_*D_];
__device__ float g_gxp[4*3*NB_*DM_];         // [kz][gate][n][unit]
__device__ int   g_ugcnt[32];                // per unit-group arrival counters
__device__ float g_h[NB_*DM_];
__device__ float g_H[NB_*TDEC_*DM_];         // 13.1 MB
// split-bf16 staging for tensor-core GEMMs
__device__ __nv_bfloat16 g_Ah[16000*1024];
__device__ __nv_bfloat16 g_Al[16000*1024];
__device__ __nv_bfloat16 g_Bh[1024*8000];
__device__ __nv_bfloat16 g_Bl[1024*8000];

__device__ __forceinline__ float tanh_approx(float x) {
    float y;
    asm("tanh.approx.f32 %0, %1;" : "=f"(y) : "f"(x));
    return y;
}

// ---------------- tensor-core primitives ------------------------------------
__device__ __forceinline__ void ldsm4(uint32_t* r, uint32_t addr) {
    asm volatile("ldmatrix.sync.aligned.m8n8.x4.shared.b16 {%0,%1,%2,%3}, [%4];"
        : "=r"(r[0]), "=r"(r[1]), "=r"(r[2]), "=r"(r[3]) : "r"(addr));
}
__device__ __forceinline__ void ldsm4t(uint32_t* r, uint32_t addr) {
    asm volatile("ldmatrix.sync.aligned.m8n8.x4.trans.shared.b16 {%0,%1,%2,%3}, [%4];"
        : "=r"(r[0]), "=r"(r[1]), "=r"(r[2]), "=r"(r[3]) : "r"(addr));
}
__device__ __forceinline__ void mma16816(float* c, const uint32_t* a, const uint32_t* b) {
    asm volatile("mma.sync.aligned.m16n8k16.row.col.f32.bf16.bf16.f32 "
        "{%0,%1,%2,%3},{%4,%5,%6,%7},{%8,%9},{%0,%1,%2,%3};"
        : "+f"(c[0]), "+f"(c[1]), "+f"(c[2]), "+f"(c[3])
        : "r"(a[0]), "r"(a[1]), "r"(a[2]), "r"(a[3]), "r"(b[0]), "r"(b[1]));
}

// ---------------- split fp32 -> (bf16 hi, bf16 lo) ---------------------------
__global__ void split_bf16(const float* __restrict__ src,
                           __nv_bfloat16* __restrict__ hi,
                           __nv_bfloat16* __restrict__ lo, int n4)
{
    int i = blockIdx.x * blockDim.x + threadIdx.x;
    if (i < n4) {
        float4 v = ((const float4*)src)[i];
        __nv_bfloat16 h0 = __float2bfloat16(v.x);
        __nv_bfloat16 h1 = __float2bfloat16(v.y);
        __nv_bfloat16 h2 = __float2bfloat16(v.z);
        __nv_bfloat16 h3 = __float2bfloat16(v.w);
        __nv_bfloat162 hh0; hh0.x = h0; hh0.y = h1;
        __nv_bfloat162 hh1; hh1.x = h2; hh1.y = h3;
        ((__nv_bfloat162*)hi)[2*i]   = hh0;
        ((__nv_bfloat162*)hi)[2*i+1] = hh1;
        __nv_bfloat162 ll0, ll1;
        ll0.x = __float2bfloat16(v.x - __bfloat162float(h0));
        ll0.y = __float2bfloat16(v.y - __bfloat162float(h1));
        ll1.x = __float2bfloat16(v.z - __bfloat162float(h2));
        ll1.y = __float2bfloat16(v.w - __bfloat162float(h3));
        ((__nv_bfloat162*)lo)[2*i]   = ll0;
        ((__nv_bfloat162*)lo)[2*i+1] = ll1;
    }
}

// ---------------- split-bf16 tensor-core GEMM --------------------------------
// C[M,N] = (Ah+Al)[M,K] @ (Bh+Bl)[K,N] + bias (drops Al*Bl)
// 128x128 tile, BK=32, 256 threads (8 warps 2x4), warp tile 64x32. 2 CTA/SM.
template <typename OutT>
__global__ __launch_bounds__(256, 2) void hgemm_split(
    const __nv_bfloat16* __restrict__ Ah, const __nv_bfloat16* __restrict__ Al,
    const __nv_bfloat16* __restrict__ Bh, const __nv_bfloat16* __restrict__ Bl,
    const float* __restrict__ bias, OutT* __restrict__ C,
    int M, int N, int K)
{
    __shared__ __nv_bfloat16 Ash[128][40];
    __shared__ __nv_bfloat16 Asl[128][40];
    __shared__ __nv_bfloat16 Bsh[32][136];
    __shared__ __nv_bfloat16 Bsl[32][136];

    const int m0 = blockIdx.x * 128;
    const int n0 = blockIdx.y * 128;
    const int tid = threadIdx.x;
    const int wid = tid >> 5, lane = tid & 31;
    const int wm = wid >> 2, wn = wid & 3;

    float acc[4][4][4] = {};

    const int arow = tid >> 2;
    const int acol = (tid & 3) * 8;
    const int bk   = tid >> 4;
    const int bcol = (tid & 15) * 8;
    const bool bok = (n0 + bcol) < N;

    const uint32_t as_h = (uint32_t)__cvta_generic_to_shared(&Ash[0][0]);
    const uint32_t as_l = (uint32_t)__cvta_generic_to_shared(&Asl[0][0]);
    const uint32_t bs_h = (uint32_t)__cvta_generic_to_shared(&Bsh[0][0]);
    const uint32_t bs_l = (uint32_t)__cvta_generic_to_shared(&Bsl[0][0]);

    const uint4 z4 = make_uint4(0u, 0u, 0u, 0u);

    for (int k0 = 0; k0 < K; k0 += 32) {
        __syncthreads();
        *(uint4*)&Ash[arow][acol] =
            *(const uint4*)(Ah + (size_t)(m0 + arow) * K + k0 + acol);
        *(uint4*)&Ash[arow+64][acol] =
            *(const uint4*)(Ah + (size_t)(m0 + arow + 64) * K + k0 + acol);
        *(uint4*)&Asl[arow][acol] =
            *(const uint4*)(Al + (size_t)(m0 + arow) * K + k0 + acol);
        *(uint4*)&Asl[arow+64][acol] =
            *(const uint4*)(Al + (size_t)(m0 + arow + 64) * K + k0 + acol);
        *(uint4*)&Bsh[bk][bcol] =
            bok ? *(const uint4*)(Bh + (size_t)(k0 + bk) * N + n0 + bcol) : z4;
        *(uint4*)&Bsh[bk+16][bcol] =
            bok ? *(const uint4*)(Bh + (size_t)(k0 + bk + 16) * N + n0 + bcol) : z4;
        *(uint4*)&Bsl[bk][bcol] =
            bok ? *(const uint4*)(Bl + (size_t)(k0 + bk) * N + n0 + bcol) : z4;
        *(uint4*)&Bsl[bk+16][bcol] =
            bok ? *(const uint4*)(Bl + (size_t)(k0 + bk + 16) * N + n0 + bcol) : z4;
        __syncthreads();

#pragma unroll
        for (int kk = 0; kk < 32; kk += 16) {
            uint32_t ah[4][4], al[4][4], bh[4][2], bl[4][2];
#pragma unroll
            for (int mt = 0; mt < 4; mt++) {
                const uint32_t off =
                    (uint32_t)(((wm*64 + mt*16 + (lane & 15)) * 40
                                + kk + ((lane >> 4) << 3)) << 1);
                ldsm4(ah[mt], as_h + off);
                ldsm4(al[mt], as_l + off);
            }
#pragma unroll
            for (int ng = 0; ng < 2; ng++) {
                const uint32_t off =
                    (uint32_t)((((kk + (lane & 15)) * 136)
                                + wn*32 + ng*16 + ((lane >> 4) << 3)) << 1);
                uint32_t r[4];
                ldsm4t(r, bs_h + off);
                bh[2*ng][0] = r[0]; bh[2*ng][1] = r[1];
                bh[2*ng+1][0] = r[2]; bh[2*ng+1][1] = r[3];
                ldsm4t(r, bs_l + off);
                bl[2*ng][0] = r[0]; bl[2*ng][1] = r[1];
                bl[2*ng+1][0] = r[2]; bl[2*ng+1][1] = r[3];
            }
#pragma unroll
            for (int mt = 0; mt < 4; mt++)
#pragma unroll
                for (int nt = 0; nt < 4; nt++) {
                    mma16816(acc[mt][nt], ah[mt], bh[nt]);
                    mma16816(acc[mt][nt], ah[mt], bl[nt]);
                    mma16816(acc[mt][nt], al[mt], bh[nt]);
                }
        }
    }

    const int tr = lane >> 2;
    const int tc = (lane & 3) * 2;
#pragma unroll
    for (int mt = 0; mt < 4; mt++) {
#pragma unroll
        for (int nt = 0; nt < 4; nt++) {
            const int col = n0 + wn*32 + nt*8 + tc;
            if (col < N) {
                const float b0 = bias[col], b1 = bias[col+1];
                const int r0 = m0 + wm*64 + mt*16 + tr;
                OutT* p0 = C + (size_t)r0 * N + col;
                OutT* p1 = C + (size_t)(r0 + 8) * N + col;
                p0[0] = (OutT)(acc[mt][nt][0] + b0);
                p0[1] = (OutT)(acc[mt][nt][1] + b1);
                p1[0] = (OutT)(acc[mt][nt][2] + b0);
                p1[1] = (OutT)(acc[mt][nt][3] + b1);
            }
        }
    }
}

// ---------------- transpose fp32 -> fp16 -------------------------------------
__global__ void transpose_f16(const float* __restrict__ src,
                              __half* __restrict__ dst,
                              int R, int ldsrc)
{
    __shared__ float tile[32][33];
    const int r0 = blockIdx.y * 32, c0 = blockIdx.x * 32;
    for (int i = threadIdx.y; i < 32; i += 8)
        tile[i][threadIdx.x] = src[(size_t)(r0 + i) * ldsrc + c0 + threadIdx.x];
    __syncthreads();
    for (int i = threadIdx.y; i < 32; i += 8)
        dst[(size_t)(c0 + i) * R + r0 + threadIdx.x] =
            __float2half(tile[threadIdx.x][i]);
}

// ---------------- fp32 -> fp16 bulk convert ---------------------------------
__global__ void f32_to_f16(const float* __restrict__ src,
                           __half* __restrict__ dst, int n4)
{
    int i = blockIdx.x * blockDim.x + threadIdx.x;
    if (i < n4) {
        float4 v = ((const float4*)src)[i];
        ((__half2*)dst)[2*i]   = __floats2half2_rn(v.x, v.y);
        ((__half2*)dst)[2*i+1] = __floats2half2_rn(v.z, v.w);
    }
}

// ---------------- embedding gather ------------------------------------------
__global__ void gather_emb(const int* __restrict__ y, const float* __restrict__ emb,
                           float* __restrict__ out)
{
    int idx = blockIdx.x * blockDim.x + threadIdx.x;
    if (idx < NB_*TDEC_*E_) {
        int row = idx >> 8;
        int e   = idx & 255;
        out[idx] = emb[(size_t)y[row] * E_ + e];
    }
}

// ---------------- skinny GEMM (q path): part[kz][n][j] = sum_k h[n][k]W2t[j][k]
__global__ __launch_bounds__(256) void gemm_skinny_h(
    const float* __restrict__ A, const __half* __restrict__ Bt,
    float* __restrict__ part, int NBcols)
{
    __shared__ float As[256][36];
    const int j0 = blockIdx.x * 32;
    const int kz = blockIdx.y;
    const int kbase = kz * 256;
    const int tid = threadIdx.x;

#pragma unroll 4
    for (int i = 0; i < 32; i++)
        As[tid][i] = A[(size_t)i * 1024 + kbase + tid];
    __syncthreads();

    const int tx = tid & 31, ty = tid >> 5;
    const int j = j0 + tx;
    const uint4* bp = (const uint4*)(Bt + (size_t)j * 1024 + kbase);

    float acc0 = 0.f, acc1 = 0.f, acc2 = 0.f, acc3 = 0.f;
#pragma unroll 4
    for (int kk = 0; kk < 256; kk += 8) {
        uint4 u = bp[kk >> 3];
        const __half2* hp = (const __half2*)&u;
        float b[8];
        float2 f0 = __half22float2(hp[0]); b[0] = f0.x; b[1] = f0.y;
        float2 f1 = __half22float2(hp[1]); b[2] = f1.x; b[3] = f1.y;
        float2 f2 = __half22float2(hp[2]); b[4] = f2.x; b[5] = f2.y;
        float2 f3 = __half22float2(hp[3]); b[6] = f3.x; b[7] = f3.y;
#pragma unroll
        for (int u8 = 0; u8 < 8; u8++) {
            float4 a = *(const float4*)&As[kk + u8][ty * 4];
            acc0 = fmaf(b[u8], a.x, acc0);
            acc1 = fmaf(b[u8], a.y, acc1);
            acc2 = fmaf(b[u8], a.z, acc2);
            acc3 = fmaf(b[u8], a.w, acc3);
        }
    }
    const int n = ty * 4;
    float* po = part + (size_t)(kz * 32 + n) * NBcols + j;
    po[0]                 = acc0;
    po[(size_t)NBcols]    = acc1;
    po[(size_t)2*NBcols]  = acc2;
    po[(size_t)3*NBcols]  = acc3;
}

// ---------------- score: s[n][t] = v . tanh(keys[n][t] + q[n]) + bv ---------
__global__ __launch_bounds__(256) void score_kernel(
    const float* __restrict__ b2, const float* __restrict__ v,
    const float* __restrict__ bv)
{
    __shared__ float qs[DM_];
    __shared__ float vs[DM_];
    const int n = blockIdx.y;
    const int tbase = blockIdx.x * 20;
    const int tid = threadIdx.x;

    for (int d = tid; d < DM_; d += 256) {
        float s = b2[d];
#pragma unroll
        for (int sp = 0; sp < 4; sp++) s += g_qpart[sp*NB_*DM_ + n*DM_ + d];
        qs[d] = s;
        vs[d] = v[d];
    }
    __syncthreads();

    const int w = tid >> 5, lane = tid & 31;
    const float bvv = bv[0];
    for (int t = tbase + w; t < tbase + 20; t += 8) {
        const uint4* kp = (const uint4*)(g_keysh + ((size_t)(n*TENC_ + t) << 10));
        float acc = 0.f;
#pragma unroll
        for (int i = 0; i < 4; i++) {
            uint4 u = kp[lane + (i << 5)];
            const __half2* hp = (const __half2*)&u;
            const int d0 = (lane + (i << 5)) << 3;
            float4 q1 = *(const float4*)&qs[d0];
            float4 q2 = *(const float4*)&qs[d0 + 4];
            float4 v1 = *(const float4*)&vs[d0];
            float4 v2 = *(const float4*)&vs[d0 + 4];
            float2 f0 = __half22float2(hp[0]);
            float2 f1 = __half22float2(hp[1]);
            float2 f2 = __half22float2(hp[2]);
            float2 f3 = __half22float2(hp[3]);
            acc = fmaf(tanh_approx(f0.x + q1.x), v1.x, acc);
            acc = fmaf(tanh_approx(f0.y + q1.y), v1.y, acc);
            acc = fmaf(tanh_approx(f1.x + q1.z), v1.z, acc);
            acc = fmaf(tanh_approx(f1.y + q1.w), v1.w, acc);
            acc = fmaf(tanh_approx(f2.x + q2.x), v2.x, acc);
            acc = fmaf(tanh_approx(f2.y + q2.y), v2.y, acc);
            acc = fmaf(tanh_approx(f3.x + q2.z), v2.z, acc);
            acc = fmaf(tanh_approx(f3.y + q2.w), v2.w, acc);
        }
#pragma unroll
        for (int off = 16; off; off >>= 1)
            acc += __shfl_xor_sync(0xffffffffu, acc, off);
        if (lane == 0) g_scores[n*TENC_ + t] = acc + bvv;
    }
}

// ---------------- softmax (redundant per block) + partial context -----------
__global__ __launch_bounds__(256) void context_part(void)
{
    __shared__ float ws[TENC_];
    __shared__ float red[256];
    const int n  = blockIdx.z;
    const int tc = blockIdx.y;
    const int d0 = blockIdx.x * 256;
    const int tid = threadIdx.x;

    float mx = -1e30f;
    for (int t = tid; t < TENC_; t += 256) {
        float s = g_scores[n*TENC_ + t];
        ws[t] = s;
        mx = fmaxf(mx, s);
    }
    red[tid] = mx; __syncthreads();
    for (int s = 128; s; s >>= 1) {
        if (tid < s) red[tid] = fmaxf(red[tid], red[tid+s]);
        __syncthreads();
    }
    mx = red[0];
    __syncthreads();
    float lsum = 0.f;
    for (int t = tid; t < TENC_; t += 256) {
        float e = __expf(ws[t] - mx);
        ws[t] = e;
        lsum += e;
    }
    red[tid] = lsum; __syncthreads();
    for (int s = 128; s; s >>= 1) {
        if (tid < s) red[tid] += red[tid+s];
        __syncthreads();
    }
    const float inv = 1.f / red[0];

    const __half* xp = g_xh + (size_t)n * TENC_ * D_ + d0 + tid;
    const int t0 = tc * 125;
    float a[5];
#pragma unroll
    for (int u = 0; u < 5; u++) a[u] = 0.f;
    for (int t = t0; t < t0 + 125; t += 5) {
#pragma unroll
        for (int u = 0; u < 5; u++)
            a[u] = fmaf(ws[t+u], __half2float(xp[(size_t)(t+u) << 10]), a[u]);
    }
    g_ctxpart[((size_t)tc * NB_ + n) * D_ + d0 + tid] =
        (((a[0]+a[1]) + (a[2]+a[3])) + a[4]) * inv;
}

// ---------------- fused gx-GEMM + GRU gate ----------------------------------
// grid (32 unit-groups, 4 kz). Each block: 32 units x 3 gates x 32 n partial.
// Last-arriving block per unit-group sums fixed-order partials + gxemb + b_rec,
// applies gate, writes h and H. Deterministic (sum order fixed).
__global__ __launch_bounds__(256) void gxgate_kernel(
    const float* __restrict__ b_rec, int t)
{
    __shared__ float As[256][36];
    __shared__ int last_flag;
    const int ug = blockIdx.x;          // unit group: units [ug*32, ug*32+32)
    const int kz = blockIdx.y;
    const int kbase = kz * 256;
    const int tid = threadIdx.x;

    // stage ctx slice: As[k][n] = sum of 4 t-chunk partials
#pragma unroll 4
    for (int i = 0; i < 32; i++) {
        float s = g_ctxpart[(size_t)i * 1024 + kbase + tid];
#pragma unroll
        for (int p = 1; p < 4; p++)
            s += g_ctxpart[(size_t)p * (NB_*D_) + (size_t)i * 1024 + kbase + tid];
        As[tid][i] = s;
    }
    __syncthreads();

    const int tx = tid & 31, ty = tid >> 5;
    const int unit = ug * 32 + tx;
    const uint4* bz = (const uint4*)(g_Wxt + (size_t)unit          * 1024 + kbase);
    const uint4* br = (const uint4*)(g_Wxt + (size_t)(1024 + unit) * 1024 + kbase);
    const uint4* bh = (const uint4*)(g_Wxt + (size_t)(2048 + unit) * 1024 + kbase);

    float az[4] = {}, ar[4] = {}, ah[4] = {};
#pragma unroll 2
    for (int kk = 0; kk < 256; kk += 8) {
        uint4 uz = bz[kk >> 3], ur = br[kk >> 3], uh = bh[kk >> 3];
        const __half2 *hz = (const __half2*)&uz, *hr = (const __half2*)&ur,
                      *hh = (const __half2*)&uh;
        float wz[8], wr[8], wh[8];
#pragma unroll
        for (int p = 0; p < 4; p++) {
            float2 fz = __half22float2(hz[p]); wz[2*p] = fz.x; wz[2*p+1] = fz.y;
            float2 fr = __half22float2(hr[p]); wr[2*p] = fr.x; wr[2*p+1] = fr.y;
            float2 fh = __half22float2(hh[p]); wh[2*p] = fh.x; wh[2*p+1] = fh.y;
        }
#pragma unroll
        for (int u8 = 0; u8 < 8; u8++) {
            float4 a = *(const float4*)&As[kk + u8][ty * 4];
#pragma unroll
            for (int i = 0; i < 4; i++) {
                float av = (&a.x)[i];
                az[i] = fmaf(wz[u8], av, az[i]);
                ar[i] = fmaf(wr[u8], av, ar[i]);
                ah[i] = fmaf(wh[u8], av, ah[i]);
            }
        }
    }

    // write partials: g_gxp[((kz*3+g)*32+n)*1024 + unit]
#pragma unroll
    for (int i = 0; i < 4; i++) {
        const int n = ty * 4 + i;
        g_gxp[((size_t)(kz*3 + 0) * NB_ + n) * DM_ + unit] = az[i];
        g_gxp[((size_t)(kz*3 + 1) * NB_ + n) * DM_ + unit] = ar[i];
        g_gxp[((size_t)(kz*3 + 2) * NB_ + n) * DM_ + unit] = ah[i];
    }
    __threadfence();
    __syncthreads();
    if (tid == 0)
        last_flag = (atomicAdd(&g_ugcnt[ug], 1) == 3);
    __syncthreads();

    if (last_flag) {
        __threadfence();
        const float brz = b_rec[unit];
        const float brr = b_rec[unit + 1024];
        const float brh = b_rec[unit + 2048];
#pragma unroll
        for (int i = 0; i < 4; i++) {
            const int n = ty * 4 + i;
            float xz = 0.f, xr = 0.f, xh = 0.f;
#pragma unroll
            for (int z = 0; z < 4; z++) {
                xz += g_gxp[((size_t)(z*3 + 0) * NB_ + n) * DM_ + unit];
                xr += g_gxp[((size_t)(z*3 + 1) * NB_ + n) * DM_ + unit];
                xh += g_gxp[((size_t)(z*3 + 2) * NB_ + n) * DM_ + unit];
            }
            const float* ge = g_gxemb + (size_t)(n*TDEC_ + t) * G3_;
            xz += ge[unit]; xr += ge[unit + 1024]; xh += ge[unit + 2048];

            float zg  = 1.f / (1.f + __expf(-(xz + brz)));
            float rg  = 1.f / (1.f + __expf(-(xr + brr)));
            float hg  = tanhf(xh + rg * brh);
            float hv  = (1.f - zg) * hg;

            g_h[n * DM_ + unit] = hv;
            g_H[(size_t)(n*TDEC_ + t) * DM_ + unit] = hv;
        }
        __syncthreads();
        if (tid == 0) g_ugcnt[ug] = 0;   // reset for next step / next replay
    }
}

// ---------------- launch -----------------------------------------------------
extern "C" void kernel_launch(void* const* d_in, const int* in_sizes, int n_in,
                              void* d_out, int out_size)
{
    (void)in_sizes; (void)n_in; (void)out_size;
    const float* x    = (const float*)d_in[0];
    const float* m    = (const float*)d_in[1];
    const int*   y    = (const int*)  d_in[2];
    const float* emb  = (const float*)d_in[3];
    const float* W1   = (const float*)d_in[4];
    const float* b1   = (const float*)d_in[5];
    const float* W2   = (const float*)d_in[6];
    const float* b2   = (const float*)d_in[7];
    const float* v    = (const float*)d_in[8];
    const float* bv   = (const float*)d_in[9];
    const float* Wx   = (const float*)d_in[10];
    // d_in[11] = Uh — provably unused (h_prev == 0)
    const float* b_in = (const float*)d_in[12];
    const float* b_rec= (const float*)d_in[13];
    const float* Wo   = (const float*)d_in[14];
    const float* bo   = (const float*)d_in[15];
    float* out = (float*)d_out;

    __half *keysh, *xh, *W2t, *Wxt;
    __nv_bfloat16 *Ah, *Al, *Bh, *Bl;
    float *yemb, *gxemb, *qpart, *h, *H;
    cudaGetSymbolAddress((void**)&keysh,  g_keysh);
    cudaGetSymbolAddress((void**)&xh,     g_xh);
    cudaGetSymbolAddress((void**)&W2t,    g_W2t);
    cudaGetSymbolAddress((void**)&Wxt,    g_Wxt);
    cudaGetSymbolAddress((void**)&yemb,   g_yemb);
    cudaGetSymbolAddress((void**)&gxemb,  g_gxemb);
    cudaGetSymbolAddress((void**)&qpart,  g_qpart);
    cudaGetSymbolAddress((void**)&h,      g_h);
    cudaGetSymbolAddress((void**)&H,      g_H);
    cudaGetSymbolAddress((void**)&Ah,     g_Ah);
    cudaGetSymbolAddress((void**)&Al,     g_Al);
    cudaGetSymbolAddress((void**)&Bh,     g_Bh);
    cudaGetSymbolAddress((void**)&Bl,     g_Bl);

    // ---- step-invariant precompute ----
    gather_emb<<<(NB_*TDEC_*E_ + 255)/256, 256>>>(y, emb, yemb);

    // keys(fp16) = x @ W1 + b1 via split-bf16 tensor cores
    split_bf16<<<(16000*1024/4 + 255)/256, 256>>>(x,  Ah, Al, 16000*1024/4);
    split_bf16<<<(1024*1024/4  + 255)/256, 256>>>(W1, Bh, Bl, 1024*1024/4);
    hgemm_split<__half><<<dim3(16000/128, 1024/128), 256>>>(
        Ah, Al, Bh, Bl, b1, keysh, 16000, 1024, 1024);

    // gxemb = yemb @ Wx[1024:1280,:] + b_in via split-bf16 tensor cores
    split_bf16<<<(3200*256/4 + 255)/256, 256>>>(yemb, Ah, Al, 3200*256/4);
    split_bf16<<<(256*3072/4 + 255)/256, 256>>>(Wx + (size_t)1024*G3_, Bh, Bl,
                                                256*3072/4);
    hgemm_split<float><<<dim3(3200/128, 3072/128), 256>>>(
        Ah, Al, Bh, Bl, b_in, gxemb, 3200, 3072, 256);

    // fp16 transposed weights + fp16 x copy for the decode loop
    transpose_f16<<<dim3(1024/32, 1024/32), dim3(32,8)>>>(W2, W2t, 1024, 1024);
    transpose_f16<<<dim3(3072/32, 1024/32), dim3(32,8)>>>(Wx, Wxt, 1024, 3072);
    f32_to_f16<<<(NB_*TENC_*D_/4 + 255)/256, 256>>>(x, xh, NB_*TENC_*D_/4);
    cudaMemcpyAsync(h, m, (size_t)NB_*DM_*sizeof(float), cudaMemcpyDeviceToDevice);

    // ---- sequential decode loop (4 kernels/step) ----
    for (int t = 0; t < TDEC_; t++) {
        gemm_skinny_h<<<dim3(DM_/32, 4), 256>>>(h, W2t, qpart, DM_);
        score_kernel<<<dim3(TENC_/20, NB_), 256>>>(b2, v, bv);
        context_part<<<dim3(4, 4, NB_), 256>>>();
        gxgate_kernel<<<dim3(32, 4), 256>>>(b_rec, t);
    }

    // ---- out = H @ Wo + bo via split-bf16 tensor cores ----
    split_bf16<<<(3200*1024/4 + 255)/256, 256>>>(H,  Ah, Al, 3200*1024/4);
    split_bf16<<<(1024*8000/4 + 255)/256, 256>>>(Wo, Bh, Bl, 1024*8000/4);
    hgemm_split<float><<<dim3(3200/128, (8000 + 127)/128), 256>>>(
        Ah, Al, Bh, Bl, bo, out, 3200, 8000, 1024);
}

// round 8
// speedup vs baseline: 2.5606x; 1.0484x over previous
#include <cuda_runtime.h>
#include <cuda_fp16.h>
#include <cuda_bf16.h>
#include <cstdint>

#define NB_   32
#define TENC_ 500
#define D_    1024
#define DM_   1024
#define TDEC_ 100
#define E_    256
#define C_    8000
#define G3_   (3*DM_)   // 3072

// ---------------- scratch (device globals; no allocations allowed) ----------
__device__ __half g_keysh[NB_*TENC_*DM_];    // 32.8 MB fp16
__device__ __half g_xh[NB_*TENC_*D_];        // 32.8 MB fp16 copy of x
__device__ __half g_W2t[DM_*DM_];            // W2^T fp16 [j][k]
__device__ __half g_Wxt[G3_*DM_];            // Wx^T (context rows) fp16 [j][k]
__device__ float g_yemb[NB_*TDEC_*E_];
__device__ float g_gxemb[NB_*TDEC_*G3_];     // 39.3 MB
__device__ float g_qpart[4*NB_*DM_];
__device__ float g_scores[NB_*TENC_];
__device__ float g_ctxpart[4*NB_*D_];
__device__ float g_gxp[4*3*NB_*DM_];         // [kz][gate][n][unit]
__device__ int   g_ugcnt[32];                // per unit-group arrival counters
__device__ float g_h[NB_*DM_];
__device__ float g_H[NB_*TDEC_*DM_];         // 13.1 MB
// split-bf16 staging for tensor-core GEMMs
__device__ __nv_bfloat16 g_Ah[16000*1024];
__device__ __nv_bfloat16 g_Al[16000*1024];
__device__ __nv_bfloat16 g_Bh[1024*8000];
__device__ __nv_bfloat16 g_Bl[1024*8000];

__device__ __forceinline__ float tanh_approx(float x) {
    float y;
    asm("tanh.approx.f32 %0, %1;" : "=f"(y) : "f"(x));
    return y;
}

// ---------------- tensor-core / async-copy primitives ------------------------
__device__ __forceinline__ void ldsm4(uint32_t* r, uint32_t addr) {
    asm volatile("ldmatrix.sync.aligned.m8n8.x4.shared.b16 {%0,%1,%2,%3}, [%4];"
        : "=r"(r[0]), "=r"(r[1]), "=r"(r[2]), "=r"(r[3]) : "r"(addr));
}
__device__ __forceinline__ void ldsm4t(uint32_t* r, uint32_t addr) {
    asm volatile("ldmatrix.sync.aligned.m8n8.x4.trans.shared.b16 {%0,%1,%2,%3}, [%4];"
        : "=r"(r[0]), "=r"(r[1]), "=r"(r[2]), "=r"(r[3]) : "r"(addr));
}
__device__ __forceinline__ void mma16816(float* c, const uint32_t* a, const uint32_t* b) {
    asm volatile("mma.sync.aligned.m16n8k16.row.col.f32.bf16.bf16.f32 "
        "{%0,%1,%2,%3},{%4,%5,%6,%7},{%8,%9},{%0,%1,%2,%3};"
        : "+f"(c[0]), "+f"(c[1]), "+f"(c[2]), "+f"(c[3])
        : "r"(a[0]), "r"(a[1]), "r"(a[2]), "r"(a[3]), "r"(b[0]), "r"(b[1]));
}
__device__ __forceinline__ void cpa16(uint32_t dst, const void* src) {
    asm volatile("cp.async.cg.shared.global [%0], [%1], 16;" :: "r"(dst), "l"(src));
}
__device__ __forceinline__ void cpa16z(uint32_t dst, const void* src, bool ok) {
    int sz = ok ? 16 : 0;
    asm volatile("cp.async.cg.shared.global [%0], [%1], 16, %2;"
                 :: "r"(dst), "l"(src), "r"(sz));
}

// ---------------- split fp32 -> (bf16 hi, bf16 lo) ---------------------------
__global__ void split_bf16(const float* __restrict__ src,
                           __nv_bfloat16* __restrict__ hi,
                           __nv_bfloat16* __restrict__ lo, int n4)
{
    int i = blockIdx.x * blockDim.x + threadIdx.x;
    if (i < n4) {
        float4 v = ((const float4*)src)[i];
        __nv_bfloat16 h0 = __float2bfloat16(v.x);
        __nv_bfloat16 h1 = __float2bfloat16(v.y);
        __nv_bfloat16 h2 = __float2bfloat16(v.z);
        __nv_bfloat16 h3 = __float2bfloat16(v.w);
        __nv_bfloat162 hh0; hh0.x = h0; hh0.y = h1;
        __nv_bfloat162 hh1; hh1.x = h2; hh1.y = h3;
        ((__nv_bfloat162*)hi)[2*i]   = hh0;
        ((__nv_bfloat162*)hi)[2*i+1] = hh1;
        __nv_bfloat162 ll0, ll1;
        ll0.x = __float2bfloat16(v.x - __bfloat162float(h0));
        ll0.y = __float2bfloat16(v.y - __bfloat162float(h1));
        ll1.x = __float2bfloat16(v.z - __bfloat162float(h2));
        ll1.y = __float2bfloat16(v.w - __bfloat162float(h3));
        ((__nv_bfloat162*)lo)[2*i]   = ll0;
        ((__nv_bfloat162*)lo)[2*i+1] = ll1;
    }
}

// ---------------- split-bf16 tensor-core GEMM, cp.async double-buffered ------
// dynamic smem: 2 buffers x (Ash 5120 | Asl 5120 | Bsh 4352 | Bsl 4352) bf16
#define HG_BUF_ELEMS 18944
#define HG_SMEM_BYTES (2 * HG_BUF_ELEMS * 2)
template <typename OutT>
__global__ __launch_bounds__(256, 2) void hgemm_split(
    const __nv_bfloat16* __restrict__ Ah, const __nv_bfloat16* __restrict__ Al,
    const __nv_bfloat16* __restrict__ Bh, const __nv_bfloat16* __restrict__ Bl,
    const float* __restrict__ bias, OutT* __restrict__ C,
    int M, int N, int K)
{
    extern __shared__ __nv_bfloat16 smem_hg[];
    const uint32_t sbase = (uint32_t)__cvta_generic_to_shared(smem_hg);

    const int m0 = blockIdx.x * 128;
    const int n0 = blockIdx.y * 128;
    const int tid = threadIdx.x;
    const int wid = tid >> 5, lane = tid & 31;
    const int wm = wid >> 2, wn = wid & 3;

    float acc[4][4][4] = {};

    const int arow = tid >> 2;            // 0..63
    const int acol = (tid & 3) * 8;       // 0,8,16,24
    const int bk   = tid >> 4;            // 0..15
    const int bcol = (tid & 15) * 8;      // 0..120
    const bool bok = (n0 + bcol) < N;

    const int nk = K >> 5;

    auto loadTile = [&](int buf, int k0) {
        const uint32_t b0 = sbase + (uint32_t)buf * (HG_BUF_ELEMS * 2);
        cpa16(b0 + (uint32_t)((arow*40 + acol) * 2),
              Ah + (size_t)(m0 + arow) * K + k0 + acol);
        cpa16(b0 + (uint32_t)(((arow+64)*40 + acol) * 2),
              Ah + (size_t)(m0 + arow + 64) * K + k0 + acol);
        const uint32_t l0 = b0 + 5120*2;
        cpa16(l0 + (uint32_t)((arow*40 + acol) * 2),
              Al + (size_t)(m0 + arow) * K + k0 + acol);
        cpa16(l0 + (uint32_t)(((arow+64)*40 + acol) * 2),
              Al + (size_t)(m0 + arow + 64) * K + k0 + acol);
        const uint32_t bh0 = b0 + 10240*2;
        cpa16z(bh0 + (uint32_t)((bk*136 + bcol) * 2),
               Bh + (size_t)(k0 + bk) * N + n0 + bcol, bok);
        cpa16z(bh0 + (uint32_t)(((bk+16)*136 + bcol) * 2),
               Bh + (size_t)(k0 + bk + 16) * N + n0 + bcol, bok);
        const uint32_t bl0 = b0 + 14592*2;
        cpa16z(bl0 + (uint32_t)((bk*136 + bcol) * 2),
               Bl + (size_t)(k0 + bk) * N + n0 + bcol, bok);
        cpa16z(bl0 + (uint32_t)(((bk+16)*136 + bcol) * 2),
               Bl + (size_t)(k0 + bk + 16) * N + n0 + bcol, bok);
        asm volatile("cp.async.commit_group;");
    };

    loadTile(0, 0);

    for (int kt = 0; kt < nk; kt++) {
        const int buf = kt & 1;
        if (kt + 1 < nk) {
            loadTile(buf ^ 1, (kt + 1) << 5);
            asm volatile("cp.async.wait_group 1;");
        } else {
            asm volatile("cp.async.wait_group 0;");
        }
        __syncthreads();

        const uint32_t bb = sbase + (uint32_t)buf * (HG_BUF_ELEMS * 2);
        const uint32_t as_h = bb;
        const uint32_t as_l = bb + 10240;
        const uint32_t bs_h = bb + 20480;
        const uint32_t bs_l = bb + 29184;

#pragma unroll
        for (int kk = 0; kk < 32; kk += 16) {
            uint32_t ah[4][4], al[4][4], bh[4][2], bl[4][2];
#pragma unroll
            for (int mt = 0; mt < 4; mt++) {
                const uint32_t off =
                    (uint32_t)(((wm*64 + mt*16 + (lane & 15)) * 40
                                + kk + ((lane >> 4) << 3)) << 1);
                ldsm4(ah[mt], as_h + off);
                ldsm4(al[mt], as_l + off);
            }
#pragma unroll
            for (int ng = 0; ng < 2; ng++) {
                const uint32_t off =
                    (uint32_t)((((kk + (lane & 15)) * 136)
                                + wn*32 + ng*16 + ((lane >> 4) << 3)) << 1);
                uint32_t r[4];
                ldsm4t(r, bs_h + off);
                bh[2*ng][0] = r[0]; bh[2*ng][1] = r[1];
                bh[2*ng+1][0] = r[2]; bh[2*ng+1][1] = r[3];
                ldsm4t(r, bs_l + off);
                bl[2*ng][0] = r[0]; bl[2*ng][1] = r[1];
                bl[2*ng+1][0] = r[2]; bl[2*ng+1][1] = r[3];
            }
#pragma unroll
            for (int mt = 0; mt < 4; mt++)
#pragma unroll
                for (int nt = 0; nt < 4; nt++) {
                    mma16816(acc[mt][nt], ah[mt], bh[nt]);
                    mma16816(acc[mt][nt], ah[mt], bl[nt]);
                    mma16816(acc[mt][nt], al[mt], bh[nt]);
                }
        }
        __syncthreads();
    }

    const int tr = lane >> 2;
    const int tc = (lane & 3) * 2;
#pragma unroll
    for (int mt = 0; mt < 4; mt++) {
#pragma unroll
        for (int nt = 0; nt < 4; nt++) {
            const int col = n0 + wn*32 + nt*8 + tc;
            if (col < N) {
                const float b0 = bias[col], b1 = bias[col+1];
                const int r0 = m0 + wm*64 + mt*16 + tr;
                OutT* p0 = C + (size_t)r0 * N + col;
                OutT* p1 = C + (size_t)(r0 + 8) * N + col;
                p0[0] = (OutT)(acc[mt][nt][0] + b0);
                p0[1] = (OutT)(acc[mt][nt][1] + b1);
                p1[0] = (OutT)(acc[mt][nt][2] + b0);
                p1[1] = (OutT)(acc[mt][nt][3] + b1);
            }
        }
    }
}

// ---------------- transpose fp32 -> fp16 -------------------------------------
__global__ void transpose_f16(const float* __restrict__ src,
                              __half* __restrict__ dst,
                              int R, int ldsrc)
{
    __shared__ float tile[32][33];
    const int r0 = blockIdx.y * 32, c0 = blockIdx.x * 32;
    for (int i = threadIdx.y; i < 32; i += 8)
        tile[i][threadIdx.x] = src[(size_t)(r0 + i) * ldsrc + c0 + threadIdx.x];
    __syncthreads();
    for (int i = threadIdx.y; i < 32; i += 8)
        dst[(size_t)(c0 + i) * R + r0 + threadIdx.x] =
            __float2half(tile[threadIdx.x][i]);
}

// ---------------- fp32 -> fp16 bulk convert ---------------------------------
__global__ void f32_to_f16(const float* __restrict__ src,
                           __half* __restrict__ dst, int n4)
{
    int i = blockIdx.x * blockDim.x + threadIdx.x;
    if (i < n4) {
        float4 v = ((const float4*)src)[i];
        ((__half2*)dst)[2*i]   = __floats2half2_rn(v.x, v.y);
        ((__half2*)dst)[2*i+1] = __floats2half2_rn(v.z, v.w);
    }
}

// ---------------- embedding gather ------------------------------------------
__global__ void gather_emb(const int* __restrict__ y, const float* __restrict__ emb,
                           float* __restrict__ out)
{
    int idx = blockIdx.x * blockDim.x + threadIdx.x;
    if (idx < NB_*TDEC_*E_) {
        int row = idx >> 8;
        int e   = idx & 255;
        out[idx] = emb[(size_t)y[row] * E_ + e];
    }
}

// ---------------- skinny GEMM (q path) — PDL --------------------------------
__global__ __launch_bounds__(256) void gemm_skinny_h(
    const float* __restrict__ A, const __half* __restrict__ Bt,
    float* __restrict__ part, int NBcols)
{
    __shared__ float As[256][36];
    const int j0 = blockIdx.x * 32;
    const int kz = blockIdx.y;
    const int kbase = kz * 256;
    const int tid = threadIdx.x;

    cudaGridDependencySynchronize();

#pragma unroll 4
    for (int i = 0; i < 32; i++)
        As[tid][i] = A[(size_t)i * 1024 + kbase + tid];
    __syncthreads();

    const int tx = tid & 31, ty = tid >> 5;
    const int j = j0 + tx;
    const uint4* bp = (const uint4*)(Bt + (size_t)j * 1024 + kbase);

    float acc0 = 0.f, acc1 = 0.f, acc2 = 0.f, acc3 = 0.f;
#pragma unroll 4
    for (int kk = 0; kk < 256; kk += 8) {
        uint4 u = bp[kk >> 3];
        const __half2* hp = (const __half2*)&u;
        float b[8];
        float2 f0 = __half22float2(hp[0]); b[0] = f0.x; b[1] = f0.y;
        float2 f1 = __half22float2(hp[1]); b[2] = f1.x; b[3] = f1.y;
        float2 f2 = __half22float2(hp[2]); b[4] = f2.x; b[5] = f2.y;
        float2 f3 = __half22float2(hp[3]); b[6] = f3.x; b[7] = f3.y;
#pragma unroll
        for (int u8 = 0; u8 < 8; u8++) {
            float4 a = *(const float4*)&As[kk + u8][ty * 4];
            acc0 = fmaf(b[u8], a.x, acc0);
            acc1 = fmaf(b[u8], a.y, acc1);
            acc2 = fmaf(b[u8], a.z, acc2);
            acc3 = fmaf(b[u8], a.w, acc3);
        }
    }
    const int n = ty * 4;
    float* po = part + (size_t)(kz * 32 + n) * NBcols + j;
    po[0]                 = acc0;
    po[(size_t)NBcols]    = acc1;
    po[(size_t)2*NBcols]  = acc2;
    po[(size_t)3*NBcols]  = acc3;
    cudaTriggerProgrammaticLaunchCompletion();
}

// ---------------- score — PDL -------------------------------------------------
__global__ __launch_bounds__(256) void score_kernel(
    const float* __restrict__ b2, const float* __restrict__ v,
    const float* __restrict__ bv)
{
    __shared__ float qs[DM_];
    __shared__ float vs[DM_];
    const int n = blockIdx.y;
    const int tbase = blockIdx.x * 20;
    const int tid = threadIdx.x;

    // independent prologue: v (input, not loop-written)
    for (int d = tid; d < DM_; d += 256) vs[d] = v[d];
    const float bvv = bv[0];

    cudaGridDependencySynchronize();

    for (int d = tid; d < DM_; d += 256) {
        float s = b2[d];
#pragma unroll
        for (int sp = 0; sp < 4; sp++) s += g_qpart[sp*NB_*DM_ + n*DM_ + d];
        qs[d] = s;
    }
    __syncthreads();

    const int w = tid >> 5, lane = tid & 31;
    for (int t = tbase + w; t < tbase + 20; t += 8) {
        const uint4* kp = (const uint4*)(g_keysh + ((size_t)(n*TENC_ + t) << 10));
        float acc = 0.f;
#pragma unroll
        for (int i = 0; i < 4; i++) {
            uint4 u = kp[lane + (i << 5)];
            const __half2* hp = (const __half2*)&u;
            const int d0 = (lane + (i << 5)) << 3;
            float4 q1 = *(const float4*)&qs[d0];
            float4 q2 = *(const float4*)&qs[d0 + 4];
            float4 v1 = *(const float4*)&vs[d0];
            float4 v2 = *(const float4*)&vs[d0 + 4];
            float2 f0 = __half22float2(hp[0]);
            float2 f1 = __half22float2(hp[1]);
            float2 f2 = __half22float2(hp[2]);
            float2 f3 = __half22float2(hp[3]);
            acc = fmaf(tanh_approx(f0.x + q1.x), v1.x, acc);
            acc = fmaf(tanh_approx(f0.y + q1.y), v1.y, acc);
            acc = fmaf(tanh_approx(f1.x + q1.z), v1.z, acc);
            acc = fmaf(tanh_approx(f1.y + q1.w), v1.w, acc);
            acc = fmaf(tanh_approx(f2.x + q2.x), v2.x, acc);
            acc = fmaf(tanh_approx(f2.y + q2.y), v2.y, acc);
            acc = fmaf(tanh_approx(f3.x + q2.z), v2.z, acc);
            acc = fmaf(tanh_approx(f3.y + q2.w), v2.w, acc);
        }
#pragma unroll
        for (int off = 16; off; off >>= 1)
            acc += __shfl_xor_sync(0xffffffffu, acc, off);
        if (lane == 0) g_scores[n*TENC_ + t] = acc + bvv;
    }
    cudaTriggerProgrammaticLaunchCompletion();
}

// ---------------- softmax + partial context — PDL ----------------------------
__global__ __launch_bounds__(256) void context_part(void)
{
    __shared__ float ws[TENC_];
    __shared__ float red[256];
    const int n  = blockIdx.z;
    const int tc = blockIdx.y;
    const int d0 = blockIdx.x * 256;
    const int tid = threadIdx.x;

    cudaGridDependencySynchronize();

    float mx = -1e30f;
    for (int t = tid; t < TENC_; t += 256) {
        float s = g_scores[n*TENC_ + t];
        ws[t] = s;
        mx = fmaxf(mx, s);
    }
    red[tid] = mx; __syncthreads();
    for (int s = 128; s; s >>= 1) {
        if (tid < s) red[tid] = fmaxf(red[tid], red[tid+s]);
        __syncthreads();
    }
    mx = red[0];
    __syncthreads();
    float lsum = 0.f;
    for (int t = tid; t < TENC_; t += 256) {
        float e = __expf(ws[t] - mx);
        ws[t] = e;
        lsum += e;
    }
    red[tid] = lsum; __syncthreads();
    for (int s = 128; s; s >>= 1) {
        if (tid < s) red[tid] += red[tid+s];
        __syncthreads();
    }
    const float inv = 1.f / red[0];

    const __half* xp = g_xh + (size_t)n * TENC_ * D_ + d0 + tid;
    const int t0 = tc * 125;
    float a[5];
#pragma unroll
    for (int u = 0; u < 5; u++) a[u] = 0.f;
    for (int t = t0; t < t0 + 125; t += 5) {
#pragma unroll
        for (int u = 0; u < 5; u++)
            a[u] = fmaf(ws[t+u], __half2float(xp[(size_t)(t+u) << 10]), a[u]);
    }
    g_ctxpart[((size_t)tc * NB_ + n) * D_ + d0 + tid] =
        (((a[0]+a[1]) + (a[2]+a[3])) + a[4]) * inv;
    cudaTriggerProgrammaticLaunchCompletion();
}

// ---------------- fused gx-GEMM + GRU gate — PDL ------------------------------
__global__ __launch_bounds__(256) void gxgate_kernel(
    const float* __restrict__ b_rec, int t)
{
    __shared__ float As[256][36];
    __shared__ int last_flag;
    const int ug = blockIdx.x;
    const int kz = blockIdx.y;
    const int kbase = kz * 256;
    const int tid = threadIdx.x;

    cudaGridDependencySynchronize();

#pragma unroll 4
    for (int i = 0; i < 32; i++) {
        float s = g_ctxpart[(size_t)i * 1024 + kbase + tid];
#pragma unroll
        for (int p = 1; p < 4; p++)
            s += g_ctxpart[(size_t)p * (NB_*D_) + (size_t)i * 1024 + kbase + tid];
        As[tid][i] = s;
    }
    __syncthreads();

    const int tx = tid & 31, ty = tid >> 5;
    const int unit = ug * 32 + tx;
    const uint4* bz = (const uint4*)(g_Wxt + (size_t)unit          * 1024 + kbase);
    const uint4* br = (const uint4*)(g_Wxt + (size_t)(1024 + unit) * 1024 + kbase);
    const uint4* bh = (const uint4*)(g_Wxt + (size_t)(2048 + unit) * 1024 + kbase);

    float az[4] = {}, ar[4] = {}, ah[4] = {};
#pragma unroll 2
    for (int kk = 0; kk < 256; kk += 8) {
        uint4 uz = bz[kk >> 3], ur = br[kk >> 3], uh = bh[kk >> 3];
        const __half2 *hz = (const __half2*)&uz, *hr = (const __half2*)&ur,
                      *hh = (const __half2*)&uh;
        float wz[8], wr[8], wh[8];
#pragma unroll
        for (int p = 0; p < 4; p++) {
            float2 fz = __half22float2(hz[p]); wz[2*p] = fz.x; wz[2*p+1] = fz.y;
            float2 fr = __half22float2(hr[p]); wr[2*p] = fr.x; wr[2*p+1] = fr.y;
            float2 fh = __half22float2(hh[p]); wh[2*p] = fh.x; wh[2*p+1] = fh.y;
        }
#pragma unroll
        for (int u8 = 0; u8 < 8; u8++) {
            float4 a = *(const float4*)&As[kk + u8][ty * 4];
#pragma unroll
            for (int i = 0; i < 4; i++) {
                float av = (&a.x)[i];
                az[i] = fmaf(wz[u8], av, az[i]);
                ar[i] = fmaf(wr[u8], av, ar[i]);
                ah[i] = fmaf(wh[u8], av, ah[i]);
            }
        }
    }

#pragma unroll
    for (int i = 0; i < 4; i++) {
        const int n = ty * 4 + i;
        g_gxp[((size_t)(kz*3 + 0) * NB_ + n) * DM_ + unit] = az[i];
        g_gxp[((size_t)(kz*3 + 1) * NB_ + n) * DM_ + unit] = ar[i];
        g_gxp[((size_t)(kz*3 + 2) * NB_ + n) * DM_ + unit] = ah[i];
    }
    __threadfence();
    __syncthreads();
    if (tid == 0)
        last_flag = (atomicAdd(&g_ugcnt[ug], 1) == 3);
    __syncthreads();

    if (last_flag) {
        __threadfence();
        const float brz = b_rec[unit];
        const float brr = b_rec[unit + 1024];
        const float brh = b_rec[unit + 2048];
#pragma unroll
        for (int i = 0; i < 4; i++) {
            const int n = ty * 4 + i;
            float xz = 0.f, xr = 0.f, xh = 0.f;
#pragma unroll
            for (int z = 0; z < 4; z++) {
                xz += g_gxp[((size_t)(z*3 + 0) * NB_ + n) * DM_ + unit];
                xr += g_gxp[((size_t)(z*3 + 1) * NB_ + n) * DM_ + unit];
                xh += g_gxp[((size_t)(z*3 + 2) * NB_ + n) * DM_ + unit];
            }
            const float* ge = g_gxemb + (size_t)(n*TDEC_ + t) * G3_;
            xz += ge[unit]; xr += ge[unit + 1024]; xh += ge[unit + 2048];

            float zg  = 1.f / (1.f + __expf(-(xz + brz)));
            float rg  = 1.f / (1.f + __expf(-(xr + brr)));
            float hg  = tanhf(xh + rg * brh);
            float hv  = (1.f - zg) * hg;

            g_h[n * DM_ + unit] = hv;
            g_H[(size_t)(n*TDEC_ + t) * DM_ + unit] = hv;
        }
        __syncthreads();
        if (tid == 0) g_ugcnt[ug] = 0;
    }
}

// ---------------- PDL launch helper ------------------------------------------
template <typename F, typename... Args>
static inline void launch_pdl(dim3 g, dim3 b, F f, Args... args)
{
    cudaLaunchAttribute attr;
    attr.id = cudaLaunchAttributeProgrammaticStreamSerialization;
    attr.val.programmaticStreamSerializationAllowed = 1;
    cudaLaunchConfig_t cfg = {};
    cfg.gridDim = g; cfg.blockDim = b;
    cfg.dynamicSmemBytes = 0;
    cfg.stream = 0;
    cfg.attrs = &attr; cfg.numAttrs = 1;
    cudaLaunchKernelEx(&cfg, f, args...);
}

// ---------------- launch -----------------------------------------------------
extern "C" void kernel_launch(void* const* d_in, const int* in_sizes, int n_in,
                              void* d_out, int out_size)
{
    (void)in_sizes; (void)n_in; (void)out_size;
    const float* x    = (const float*)d_in[0];
    const float* m    = (const float*)d_in[1];
    const int*   y    = (const int*)  d_in[2];
    const float* emb  = (const float*)d_in[3];
    const float* W1   = (const float*)d_in[4];
    const float* b1   = (const float*)d_in[5];
    const float* W2   = (const float*)d_in[6];
    const float* b2   = (const float*)d_in[7];
    const float* v    = (const float*)d_in[8];
    const float* bv   = (const float*)d_in[9];
    const float* Wx   = (const float*)d_in[10];
    // d_in[11] = Uh — provably unused (h_prev == 0)
    const float* b_in = (const float*)d_in[12];
    const float* b_rec= (const float*)d_in[13];
    const float* Wo   = (const float*)d_in[14];
    const float* bo   = (const float*)d_in[15];
    float* out = (float*)d_out;

    __half *keysh, *xh, *W2t, *Wxt;
    __nv_bfloat16 *Ah, *Al, *Bh, *Bl;
    float *yemb, *gxemb, *qpart, *h, *H;
    cudaGetSymbolAddress((void**)&keysh,  g_keysh);
    cudaGetSymbolAddress((void**)&xh,     g_xh);
    cudaGetSymbolAddress((void**)&W2t,    g_W2t);
    cudaGetSymbolAddress((void**)&Wxt,    g_Wxt);
    cudaGetSymbolAddress((void**)&yemb,   g_yemb);
    cudaGetSymbolAddress((void**)&gxemb,  g_gxemb);
    cudaGetSymbolAddress((void**)&qpart,  g_qpart);
    cudaGetSymbolAddress((void**)&h,      g_h);
    cudaGetSymbolAddress((void**)&H,      g_H);
    cudaGetSymbolAddress((void**)&Ah,     g_Ah);
    cudaGetSymbolAddress((void**)&Al,     g_Al);
    cudaGetSymbolAddress((void**)&Bh,     g_Bh);
    cudaGetSymbolAddress((void**)&Bl,     g_Bl);

    cudaFuncSetAttribute(hgemm_split<__half>,
        cudaFuncAttributeMaxDynamicSharedMemorySize, HG_SMEM_BYTES);
    cudaFuncSetAttribute(hgemm_split<float>,
        cudaFuncAttributeMaxDynamicSharedMemorySize, HG_SMEM_BYTES);

    // ---- step-invariant precompute ----
    gather_emb<<<(NB_*TDEC_*E_ + 255)/256, 256>>>(y, emb, yemb);

    split_bf16<<<(16000*1024/4 + 255)/256, 256>>>(x,  Ah, Al, 16000*1024/4);
    split_bf16<<<(1024*1024/4  + 255)/256, 256>>>(W1, Bh, Bl, 1024*1024/4);
    hgemm_split<__half><<<dim3(16000/128, 1024/128), 256, HG_SMEM_BYTES>>>(
        Ah, Al, Bh, Bl, b1, keysh, 16000, 1024, 1024);

    split_bf16<<<(3200*256/4 + 255)/256, 256>>>(yemb, Ah, Al, 3200*256/4);
    split_bf16<<<(256*3072/4 + 255)/256, 256>>>(Wx + (size_t)1024*G3_, Bh, Bl,
                                                256*3072/4);
    hgemm_split<float><<<dim3(3200/128, 3072/128), 256, HG_SMEM_BYTES>>>(
        Ah, Al, Bh, Bl, b_in, gxemb, 3200, 3072, 256);

    transpose_f16<<<dim3(1024/32, 1024/32), dim3(32,8)>>>(W2, W2t, 1024, 1024);
    transpose_f16<<<dim3(3072/32, 1024/32), dim3(32,8)>>>(Wx, Wxt, 1024, 3072);
    f32_to_f16<<<(NB_*TENC_*D_/4 + 255)/256, 256>>>(x, xh, NB_*TENC_*D_/4);
    cudaMemcpyAsync(h, m, (size_t)NB_*DM_*sizeof(float), cudaMemcpyDeviceToDevice);

    // ---- sequential decode loop (4 PDL kernels/step) ----
    for (int t = 0; t < TDEC_; t++) {
        launch_pdl(dim3(DM_/32, 4), dim3(256), gemm_skinny_h,
                   (const float*)h, (const __half*)W2t, qpart, (int)DM_);
        launch_pdl(dim3(TENC_/20, NB_), dim3(256), score_kernel, b2, v, bv);
        launch_pdl(dim3(4, 4, NB_), dim3(256), context_part);
        launch_pdl(dim3(32, 4), dim3(256), gxgate_kernel, b_rec, t);
    }

    // ---- out = H @ Wo + bo via split-bf16 tensor cores ----
    split_bf16<<<(3200*1024/4 + 255)/256, 256>>>(H,  Ah, Al, 3200*1024/4);
    split_bf16<<<(1024*8000/4 + 255)/256, 256>>>(Wo, Bh, Bl, 1024*8000/4);
    hgemm_split<float><<<dim3(3200/128, (8000 + 127)/128), 256, HG_SMEM_BYTES>>>(
        Ah, Al, Bh, Bl, bo, out, 3200, 8000, 1024);
}